// round 1
// baseline (speedup 1.0000x reference)
#include <cuda_runtime.h>

// Problem constants (from reference)
#define NN   20000
#define EE   640000
#define FIN  128
#define FOUT 128
#define RR   65
#define BB   65
#define TILE_E 32
#define NBN  100   // BN partial blocks (200 rows each)

// ---------------- scratch (__device__ globals; no allocs allowed) ----------
__device__ float g_W[(size_t)RR * FIN * FOUT];          // 4.26 MB
__device__ int   g_cnt[RR];
__device__ int   g_rcur[RR];
__device__ int   g_estart[RR + 1];
__device__ int   g_tstart[RR + 1];
__device__ int   g_perm[EE];
__device__ int   g_dcnt[NN];
__device__ int   g_dcur[NN];
__device__ int   g_dstart[NN + 1];
__device__ int   g_dperm[EE];
__device__ float g_edge_out[(size_t)EE * FOUT];         // 327.7 MB
__device__ float g_h[(size_t)NN * FOUT];                // 10.2 MB
__device__ float g_psum[NBN * FOUT];
__device__ float g_psq[NBN * FOUT];
__device__ float g_scale[FOUT];
__device__ float g_shift[FOUT];

// ---------------- K0: zero counters ----------------------------------------
__global__ void k_init() {
    int i = blockIdx.x * 256 + threadIdx.x;
    if (i < RR) { g_cnt[i] = 0; g_rcur[i] = 0; }
    if (i < NN) { g_dcnt[i] = 0; g_dcur[i] = 0; }
}

// ---------------- K1: W[r,i,o] = sum_b comp[r,b] * basis[b,i,o] -------------
__global__ __launch_bounds__(128) void k_w(const float* __restrict__ basis,
                                           const float* __restrict__ comp) {
    __shared__ float sc[BB];
    int blk = blockIdx.x;          // r*128 + i
    int r = blk >> 7, i = blk & 127;
    int o = threadIdx.x;
    if (o < BB) sc[o] = comp[r * BB + o];
    __syncthreads();
    float acc = 0.f;
    const float* bp = basis + (size_t)i * FOUT + o;
    #pragma unroll 5
    for (int b = 0; b < BB; b++)
        acc += sc[b] * bp[(size_t)b * FIN * FOUT];
    g_W[((size_t)r * FIN + i) * FOUT + o] = acc;
}

// ---------------- K2: histograms (relation + dst) ---------------------------
__global__ void k_hist(const int* __restrict__ etype, const int* __restrict__ dst) {
    __shared__ int sh[RR];
    int tid = threadIdx.x;
    if (tid < RR) sh[tid] = 0;
    __syncthreads();
    int e = blockIdx.x * 256 + tid;
    if (e < EE) {
        atomicAdd(&sh[etype[e]], 1);
        atomicAdd(&g_dcnt[dst[e]], 1);
    }
    __syncthreads();
    if (tid < RR && sh[tid]) atomicAdd(&g_cnt[tid], sh[tid]);
}

// ---------------- K3: scans (relation serial; dst 20000-wide) ---------------
__global__ __launch_bounds__(1024) void k_scan() {
    __shared__ int sp[1024];
    int t = threadIdx.x;
    int base = t * 20;
    int s = 0;
    for (int j = 0; j < 20; j++) {
        int idx = base + j;
        if (idx < NN) s += g_dcnt[idx];
    }
    sp[t] = s;
    __syncthreads();
    for (int off = 1; off < 1024; off <<= 1) {
        int v = (t >= off) ? sp[t - off] : 0;
        __syncthreads();
        sp[t] += v;
        __syncthreads();
    }
    int run = (t > 0) ? sp[t - 1] : 0;
    for (int j = 0; j < 20; j++) {
        int idx = base + j;
        if (idx < NN) { g_dstart[idx] = run; run += g_dcnt[idx]; }
    }
    if (t == 1023) g_dstart[NN] = run;
    if (t == 0) {
        int es = 0, ts = 0;
        for (int r = 0; r < RR; r++) {
            g_estart[r] = es; g_tstart[r] = ts;
            es += g_cnt[r];
            ts += (g_cnt[r] + TILE_E - 1) / TILE_E;
        }
        g_estart[RR] = es; g_tstart[RR] = ts;
    }
}

// ---------------- K4: scatter (counting sort by rel, and by dst) ------------
__global__ void k_scatter(const int* __restrict__ etype, const int* __restrict__ dst) {
    __shared__ int s_cnt[RR], s_base[RR];
    int tid = threadIdx.x;
    if (tid < RR) s_cnt[tid] = 0;
    __syncthreads();
    int e = blockIdx.x * 256 + tid;
    bool valid = (e < EE);
    int r = 0, lrank = 0;
    if (valid) { r = etype[e]; lrank = atomicAdd(&s_cnt[r], 1); }
    __syncthreads();
    if (tid < RR && s_cnt[tid] > 0) s_base[tid] = atomicAdd(&g_rcur[tid], s_cnt[tid]);
    __syncthreads();
    if (valid) {
        g_perm[g_estart[r] + s_base[r] + lrank] = e;
        int d = dst[e];
        int dpos = g_dstart[d] + atomicAdd(&g_dcur[d], 1);
        g_dperm[dpos] = e;
    }
}

// ---------------- K5: relation-tiled GEMM ----------------------------------
// Each block: 32 edges of one relation x full 128x128 W_r.
// 256 threads, per-thread 4x4 register tile. Output -> g_edge_out[eid].
__global__ __launch_bounds__(256) void k_gemm(const float* __restrict__ x,
                                              const int* __restrict__ src,
                                              const float* __restrict__ norm) {
    __shared__ float sAT[128][36];   // [k][edge], padded to keep f4 alignment
    __shared__ int   s_eid[TILE_E];
    __shared__ float s_nrm[TILE_E];
    __shared__ int   s_info[3];

    int tid = threadIdx.x;
    int t = blockIdx.x;
    if (t >= g_tstart[RR]) return;   // uniform per block

    if (tid == 0) {
        int r = 0;
        while (!(t >= g_tstart[r] && t < g_tstart[r + 1])) r++;
        int base = g_estart[r] + (t - g_tstart[r]) * TILE_E;
        int cnt = g_estart[r + 1] - base;
        if (cnt > TILE_E) cnt = TILE_E;
        s_info[0] = r; s_info[1] = base; s_info[2] = cnt;
    }
    __syncthreads();
    int r = s_info[0], base = s_info[1], cnt = s_info[2];

    if (tid < TILE_E) {
        int eid = -1; float nm = 0.f;
        if (tid < cnt) { eid = g_perm[base + tid]; nm = norm[eid]; }
        s_eid[tid] = eid; s_nrm[tid] = nm;
    }
    __syncthreads();

    // gather 32 rows of x (scaled by norm) into transposed smem
    for (int idx = tid; idx < TILE_E * 32; idx += 256) {
        int i = idx & 31;          // edge slot
        int j = idx >> 5;          // float4 chunk (k/4)
        float4 v = make_float4(0.f, 0.f, 0.f, 0.f);
        int eid = s_eid[i];
        if (eid >= 0) {
            const float4* xr = (const float4*)(x + (size_t)src[eid] * FIN);
            v = __ldg(&xr[j]);
            float nm = s_nrm[i];
            v.x *= nm; v.y *= nm; v.z *= nm; v.w *= nm;
        }
        int k = j << 2;
        sAT[k + 0][i] = v.x; sAT[k + 1][i] = v.y;
        sAT[k + 2][i] = v.z; sAT[k + 3][i] = v.w;
    }
    __syncthreads();

    int tx = tid & 31;      // output col group (4 cols)
    int ty = tid >> 5;      // edge group (4 edges)
    const float4* Wr = (const float4*)(g_W + (size_t)r * FIN * FOUT);

    float c00=0,c01=0,c02=0,c03=0, c10=0,c11=0,c12=0,c13=0;
    float c20=0,c21=0,c22=0,c23=0, c30=0,c31=0,c32=0,c33=0;

    #pragma unroll 4
    for (int k = 0; k < 128; k++) {
        float4 b = __ldg(&Wr[(k << 5) + tx]);
        float4 a = *(const float4*)&sAT[k][ty << 2];
        c00 += a.x*b.x; c01 += a.x*b.y; c02 += a.x*b.z; c03 += a.x*b.w;
        c10 += a.y*b.x; c11 += a.y*b.y; c12 += a.y*b.z; c13 += a.y*b.w;
        c20 += a.z*b.x; c21 += a.z*b.y; c22 += a.z*b.z; c23 += a.z*b.w;
        c30 += a.w*b.x; c31 += a.w*b.y; c32 += a.w*b.z; c33 += a.w*b.w;
    }

    float4 rows[4] = {
        make_float4(c00, c01, c02, c03),
        make_float4(c10, c11, c12, c13),
        make_float4(c20, c21, c22, c23),
        make_float4(c30, c31, c32, c33)
    };
    #pragma unroll
    for (int i = 0; i < 4; i++) {
        int eid = s_eid[(ty << 2) + i];
        if (eid >= 0)
            *(float4*)(g_edge_out + (size_t)eid * FOUT + (tx << 2)) = rows[i];
    }
}

// ---------------- K6: per-node segmented reduce + bias/relu + residual ------
__global__ __launch_bounds__(128) void k_reduce(const float* __restrict__ x,
                                                const float* __restrict__ h_bias,
                                                const float* __restrict__ W_res,
                                                const float* __restrict__ b_res) {
    __shared__ float sx[FIN];
    int n = blockIdx.x, o = threadIdx.x;
    sx[o] = x[(size_t)n * FIN + o];
    __syncthreads();

    float acc = 0.f;
    int s = g_dstart[n], e = g_dstart[n + 1];
    for (int j = s; j < e; j++)
        acc += g_edge_out[(size_t)g_dperm[j] * FOUT + o];
    acc += __ldg(&h_bias[o]);
    acc = fmaxf(acc, 0.f);

    float rr = __ldg(&b_res[o]);
    #pragma unroll 8
    for (int k = 0; k < FIN; k++)
        rr += sx[k] * __ldg(&W_res[k * FOUT + o]);
    acc += fmaxf(rr, 0.f);

    g_h[(size_t)n * FOUT + o] = acc;
}

// ---------------- K7: BN partial sums (deterministic two-stage) -------------
__global__ __launch_bounds__(128) void k_bnsum() {
    int b = blockIdx.x, o = threadIdx.x;
    float s = 0.f, sq = 0.f;
    int r0 = b * (NN / NBN), r1 = r0 + (NN / NBN);
    for (int n = r0; n < r1; n++) {
        float v = g_h[(size_t)n * FOUT + o];
        s += v; sq += v * v;
    }
    g_psum[b * FOUT + o] = s;
    g_psq[b * FOUT + o] = sq;
}

// ---------------- K8: BN finalize -------------------------------------------
__global__ __launch_bounds__(128) void k_bnfin(const float* __restrict__ gamma,
                                               const float* __restrict__ beta) {
    int o = threadIdx.x;
    float s = 0.f, sq = 0.f;
    for (int b = 0; b < NBN; b++) { s += g_psum[b * FOUT + o]; sq += g_psq[b * FOUT + o]; }
    float mean = s / (float)NN;
    float var = sq / (float)NN - mean * mean;
    float sc = gamma[o] * rsqrtf(var + 1e-5f);
    g_scale[o] = sc;
    g_shift[o] = beta[o] - mean * sc;
}

// ---------------- K9: apply BN ----------------------------------------------
__global__ void k_out(float* __restrict__ out) {
    int i = blockIdx.x * 256 + threadIdx.x;
    if (i < NN * FOUT) {
        int o = i & 127;
        out[i] = g_h[i] * g_scale[o] + g_shift[o];
    }
}

// ---------------- launch ------------------------------------------------------
extern "C" void kernel_launch(void* const* d_in, const int* in_sizes, int n_in,
                              void* d_out, int out_size) {
    const float* node_feats = (const float*)d_in[0];
    const int*   src        = (const int*)d_in[1];
    const int*   dst        = (const int*)d_in[2];
    const int*   etype      = (const int*)d_in[3];
    const float* norm       = (const float*)d_in[4];
    const float* basis      = (const float*)d_in[5];
    const float* comp       = (const float*)d_in[6];
    const float* h_bias     = (const float*)d_in[7];
    const float* W_res      = (const float*)d_in[8];
    const float* b_res      = (const float*)d_in[9];
    const float* gamma      = (const float*)d_in[10];
    const float* beta       = (const float*)d_in[11];
    float* out = (float*)d_out;

    k_init<<<(NN + 255) / 256, 256>>>();
    k_w<<<RR * FIN, 128>>>(basis, comp);
    k_hist<<<(EE + 255) / 256, 256>>>(etype, dst);
    k_scan<<<1, 1024>>>();
    k_scatter<<<(EE + 255) / 256, 256>>>(etype, dst);
    // worst-case tile count: E/TILE_E + one partial tile per relation
    k_gemm<<<EE / TILE_E + RR, 256>>>(node_feats, src, norm);
    k_reduce<<<NN, 128>>>(node_feats, h_bias, W_res, b_res);
    k_bnsum<<<NBN, 128>>>();
    k_bnfin<<<1, 128>>>(gamma, beta);
    k_out<<<(NN * FOUT + 255) / 256, 256>>>(out);
    (void)in_sizes; (void)n_in; (void)out_size;
}

// round 3
// speedup vs baseline: 1.9486x; 1.9486x over previous
#include <cuda_runtime.h>
#include <cuda_bf16.h>
#include <stdint.h>

// Problem constants
#define NN   20000
#define EE   640000
#define FIN  128
#define FOUT 128
#define RR   65
#define BB   65
#define TILE_M 128
#define NT_GEMM (EE / TILE_M + RR)
#define NBN  100

#define ROWB 272          // bytes per smem row (136 bf16, padded)
#define ATILE (128 * ROWB)

// ---------------- scratch (__device__ globals) ------------------------------
__device__ float g_W[(size_t)RR * FIN * FOUT];
__device__ __align__(16) __nv_bfloat16 g_WT_hi[(size_t)RR * FOUT * FIN]; // [r][o][k]
__device__ __align__(16) __nv_bfloat16 g_WT_lo[(size_t)RR * FOUT * FIN];
__device__ int   g_cnt[RR];
__device__ int   g_rcur[RR];
__device__ int   g_estart[RR + 1];
__device__ int   g_tstart[RR + 1];
__device__ int   g_perm[EE];
__device__ int   g_dcnt[NN];
__device__ int   g_dcur[NN];
__device__ int   g_dstart[NN + 1];
__device__ int   g_dperm[EE];
__device__ float g_edge_out[(size_t)EE * FOUT];
__device__ float g_res[(size_t)NN * FOUT];
__device__ float g_h[(size_t)NN * FOUT];
__device__ float g_psum[NBN * FOUT];
__device__ float g_psq[NBN * FOUT];
__device__ float g_scale[FOUT];
__device__ float g_shift[FOUT];

// ---------------- helpers ----------------------------------------------------
__device__ __forceinline__ uint32_t smem_u32(const void* p) {
    uint32_t a;
    asm("{ .reg .u64 t; cvta.to.shared.u64 t, %1; cvt.u32.u64 %0, t; }"
        : "=r"(a) : "l"(p));
    return a;
}

__device__ __forceinline__ void ldsm_x4(uint32_t addr, uint32_t& r0, uint32_t& r1,
                                        uint32_t& r2, uint32_t& r3) {
    asm volatile("ldmatrix.sync.aligned.m8n8.x4.shared.b16 {%0,%1,%2,%3}, [%4];"
                 : "=r"(r0), "=r"(r1), "=r"(r2), "=r"(r3) : "r"(addr));
}

__device__ __forceinline__ void mma16816(float* c, const uint32_t* a,
                                         uint32_t b0, uint32_t b1) {
    asm volatile(
        "mma.sync.aligned.m16n8k16.row.col.f32.bf16.bf16.f32 "
        "{%0,%1,%2,%3}, {%4,%5,%6,%7}, {%8,%9}, {%0,%1,%2,%3};"
        : "+f"(c[0]), "+f"(c[1]), "+f"(c[2]), "+f"(c[3])
        : "r"(a[0]), "r"(a[1]), "r"(a[2]), "r"(a[3]), "r"(b0), "r"(b1));
}

// split fp32 pair -> packed bf16 hi / lo
__device__ __forceinline__ void cvt2(float a, float b, uint32_t& h, uint32_t& l) {
    __nv_bfloat16 ha = __float2bfloat16(a), hb = __float2bfloat16(b);
    __nv_bfloat16 la = __float2bfloat16(a - __bfloat162float(ha));
    __nv_bfloat16 lb = __float2bfloat16(b - __bfloat162float(hb));
    h = ((uint32_t)__bfloat16_as_ushort(hb) << 16) | (uint32_t)__bfloat16_as_ushort(ha);
    l = ((uint32_t)__bfloat16_as_ushort(lb) << 16) | (uint32_t)__bfloat16_as_ushort(la);
}

// ---------------- K0 ----------------------------------------------------------
__global__ void k_init() {
    int i = blockIdx.x * 256 + threadIdx.x;
    if (i < RR) { g_cnt[i] = 0; g_rcur[i] = 0; }
    if (i < NN) { g_dcnt[i] = 0; g_dcur[i] = 0; }
}

// ---------------- K1: W = comp x basis; bf16 hi/lo transposed -----------------
__global__ __launch_bounds__(128) void k_w(const float* __restrict__ basis,
                                           const float* __restrict__ comp) {
    __shared__ float sc[BB];
    int blk = blockIdx.x;          // r*128 + i
    int r = blk >> 7, i = blk & 127;
    int o = threadIdx.x;
    if (o < BB) sc[o] = comp[r * BB + o];
    __syncthreads();
    float acc = 0.f;
    const float* bp = basis + (size_t)i * FOUT + o;
    #pragma unroll 5
    for (int b = 0; b < BB; b++)
        acc += sc[b] * bp[(size_t)b * FIN * FOUT];
    g_W[((size_t)r * FIN + i) * FOUT + o] = acc;
    __nv_bfloat16 hi = __float2bfloat16(acc);
    __nv_bfloat16 lo = __float2bfloat16(acc - __bfloat162float(hi));
    size_t tidx = ((size_t)r * FOUT + o) * FIN + i;
    g_WT_hi[tidx] = hi;
    g_WT_lo[tidx] = lo;
}

// ---------------- K2: histograms ------------------------------------------------
__global__ void k_hist(const int* __restrict__ etype, const int* __restrict__ dst) {
    __shared__ int sh[RR];
    int tid = threadIdx.x;
    if (tid < RR) sh[tid] = 0;
    __syncthreads();
    int e = blockIdx.x * 256 + tid;
    if (e < EE) {
        atomicAdd(&sh[etype[e]], 1);
        atomicAdd(&g_dcnt[dst[e]], 1);
    }
    __syncthreads();
    if (tid < RR && sh[tid]) atomicAdd(&g_cnt[tid], sh[tid]);
}

// ---------------- K3: scans ------------------------------------------------------
__global__ __launch_bounds__(1024) void k_scan() {
    __shared__ int sp[1024];
    int t = threadIdx.x;
    int base = t * 20;
    int s = 0;
    for (int j = 0; j < 20; j++) {
        int idx = base + j;
        if (idx < NN) s += g_dcnt[idx];
    }
    sp[t] = s;
    __syncthreads();
    for (int off = 1; off < 1024; off <<= 1) {
        int v = (t >= off) ? sp[t - off] : 0;
        __syncthreads();
        sp[t] += v;
        __syncthreads();
    }
    int run = (t > 0) ? sp[t - 1] : 0;
    for (int j = 0; j < 20; j++) {
        int idx = base + j;
        if (idx < NN) { g_dstart[idx] = run; run += g_dcnt[idx]; }
    }
    if (t == 1023) g_dstart[NN] = run;
    if (t == 0) {
        int es = 0, ts = 0;
        for (int r = 0; r < RR; r++) {
            g_estart[r] = es; g_tstart[r] = ts;
            es += g_cnt[r];
            ts += (g_cnt[r] + TILE_M - 1) / TILE_M;
        }
        g_estart[RR] = es; g_tstart[RR] = ts;
    }
}

// ---------------- K4: scatter ------------------------------------------------------
__global__ void k_scatter(const int* __restrict__ etype, const int* __restrict__ dst) {
    __shared__ int s_cnt[RR], s_base[RR];
    int tid = threadIdx.x;
    if (tid < RR) s_cnt[tid] = 0;
    __syncthreads();
    int e = blockIdx.x * 256 + tid;
    bool valid = (e < EE);
    int r = 0, lrank = 0;
    if (valid) { r = etype[e]; lrank = atomicAdd(&s_cnt[r], 1); }
    __syncthreads();
    if (tid < RR && s_cnt[tid] > 0) s_base[tid] = atomicAdd(&g_rcur[tid], s_cnt[tid]);
    __syncthreads();
    if (valid) {
        g_perm[g_estart[r] + s_base[r] + lrank] = e;
        int d = dst[e];
        int dpos = g_dstart[d] + atomicAdd(&g_dcur[d], 1);
        g_dperm[dpos] = e;
    }
}

// ---------------- K5: HMMA bf16-split GEMM (mma.sync m16n8k16) -----------------
// CTA: 128 edges x 128 out, K=128. 8 warps 4(M)x2(N); warp tile 32x64.
// D = Ah*Bh + Al*Bh + Ah*Bl (fp32 acc) -> g_edge_out.
__global__ __launch_bounds__(256) void k_gemm(const float* __restrict__ x,
                                              const int* __restrict__ src,
                                              const float* __restrict__ norm) {
    extern __shared__ char dsm[];
    __shared__ int   s_eid[TILE_M];
    __shared__ int   s_src[TILE_M];
    __shared__ float s_nrm[TILE_M];
    __shared__ int   s_info[3];

    char* A_hi = dsm;
    char* A_lo = dsm + ATILE;
    char* B_hi = dsm + 2 * ATILE;
    char* B_lo = dsm + 3 * ATILE;

    int tid = threadIdx.x;
    int t = blockIdx.x;
    if (t >= g_tstart[RR]) return;    // uniform per block

    if (tid == 0) {
        int r = 0;
        while (!(t >= g_tstart[r] && t < g_tstart[r + 1])) r++;
        int ebase = g_estart[r] + (t - g_tstart[r]) * TILE_M;
        int cnt = g_estart[r + 1] - ebase;
        if (cnt > TILE_M) cnt = TILE_M;
        s_info[0] = r; s_info[1] = ebase; s_info[2] = cnt;
    }
    __syncthreads();
    int r = s_info[0], ebase = s_info[1], cnt = s_info[2];

    if (tid < TILE_M) {
        int eid = -1, sv = 0; float nm = 0.f;
        if (tid < cnt) { eid = g_perm[ebase + tid]; sv = src[eid]; nm = norm[eid]; }
        s_eid[tid] = eid; s_src[tid] = sv; s_nrm[tid] = nm;
    }
    __syncthreads();

    // ---- B fill: WT hi/lo [128 o][128 k] -> padded rows -----------------------
    const uint4* WH = (const uint4*)(g_WT_hi + (size_t)r * FOUT * FIN);
    const uint4* WL = (const uint4*)(g_WT_lo + (size_t)r * FOUT * FIN);
    #pragma unroll
    for (int it = 0; it < 16; it++) {
        int id = tid + it * 256;             // 0..4095
        int arr = id >> 11;
        int o = (id >> 4) & 127;
        int j = id & 15;
        uint4 v = arr ? __ldg(&WL[o * 16 + j]) : __ldg(&WH[o * 16 + j]);
        *(uint4*)((arr ? B_lo : B_hi) + o * ROWB + j * 16) = v;
    }

    // ---- A fill: gather x[src]*norm, split bf16 hi/lo --------------------------
    #pragma unroll
    for (int it = 0; it < 8; it++) {
        int id = tid + it * 256;             // 0..2047
        int m = id >> 4, j = id & 15;        // edge row, 16B k-chunk
        float4 v0 = make_float4(0.f, 0.f, 0.f, 0.f), v1 = v0;
        if (s_eid[m] >= 0) {
            const float4* xr = (const float4*)(x + (size_t)s_src[m] * FIN);
            v0 = __ldg(xr + 2 * j); v1 = __ldg(xr + 2 * j + 1);
            float nm = s_nrm[m];
            v0.x *= nm; v0.y *= nm; v0.z *= nm; v0.w *= nm;
            v1.x *= nm; v1.y *= nm; v1.z *= nm; v1.w *= nm;
        }
        uint4 h4, l4;
        cvt2(v0.x, v0.y, h4.x, l4.x);
        cvt2(v0.z, v0.w, h4.y, l4.y);
        cvt2(v1.x, v1.y, h4.z, l4.z);
        cvt2(v1.z, v1.w, h4.w, l4.w);
        int off = m * ROWB + j * 16;
        *(uint4*)(A_hi + off) = h4;
        *(uint4*)(A_lo + off) = l4;
    }
    __syncthreads();

    // ---- mainloop ----------------------------------------------------------------
    int lane = tid & 31, w = tid >> 5;
    int wm = w & 3, wn = w >> 2;             // 4 M-groups, 2 N-groups
    int rm = wm * 32;

    float acc[2][8][4];
    #pragma unroll
    for (int a = 0; a < 2; a++)
        #pragma unroll
        for (int b = 0; b < 8; b++)
            #pragma unroll
            for (int c = 0; c < 4; c++) acc[a][b][c] = 0.f;

    uint32_t aBaseHi = smem_u32(A_hi), aBaseLo = smem_u32(A_lo);
    uint32_t bBaseHi = smem_u32(B_hi), bBaseLo = smem_u32(B_lo);

    // lane-fixed address components
    uint32_t aLane = (uint32_t)((rm + (lane & 15)) * ROWB + ((lane >> 4) << 4));
    uint32_t bLane = (uint32_t)((wn * 64 + ((lane >> 4) << 3) + (lane & 7)) * ROWB
                                + (((lane >> 3) & 1) << 4));

    #pragma unroll 1
    for (int p = 0; p < 3; p++) {
        uint32_t aB = (p == 1) ? aBaseLo : aBaseHi;
        uint32_t bB = (p == 2) ? bBaseLo : bBaseHi;
        uint32_t aAddr = aB + aLane;
        uint32_t bAddr = bB + bLane;
        #pragma unroll
        for (int s = 0; s < 8; s++) {
            uint32_t ka = aAddr + s * 32;
            uint32_t kb = bAddr + s * 32;
            uint32_t a0[4], a1[4];
            ldsm_x4(ka,             a0[0], a0[1], a0[2], a0[3]);
            ldsm_x4(ka + 16 * ROWB, a1[0], a1[1], a1[2], a1[3]);
            #pragma unroll
            for (int pr = 0; pr < 4; pr++) {
                uint32_t b0, b1, b2, b3;
                ldsm_x4(kb + pr * 16 * ROWB, b0, b1, b2, b3);
                int nt = pr * 2;
                mma16816(acc[0][nt],     a0, b0, b1);
                mma16816(acc[1][nt],     a1, b0, b1);
                mma16816(acc[0][nt + 1], a0, b2, b3);
                mma16816(acc[1][nt + 1], a1, b2, b3);
            }
        }
    }

    // ---- epilogue: write fp32 rows to g_edge_out ----------------------------------
    int colBase = wn * 64 + (lane & 3) * 2;
    #pragma unroll
    for (int mt = 0; mt < 2; mt++) {
        int row0 = rm + mt * 16 + (lane >> 2);
        int e0 = s_eid[row0], e1 = s_eid[row0 + 8];
        float* p0 = (e0 >= 0) ? g_edge_out + (size_t)e0 * FOUT + colBase : (float*)0;
        float* p1 = (e1 >= 0) ? g_edge_out + (size_t)e1 * FOUT + colBase : (float*)0;
        #pragma unroll
        for (int nt = 0; nt < 8; nt++) {
            if (p0) *(float2*)(p0 + nt * 8) = make_float2(acc[mt][nt][0], acc[mt][nt][1]);
            if (p1) *(float2*)(p1 + nt * 8) = make_float2(acc[mt][nt][2], acc[mt][nt][3]);
        }
    }
}

// ---------------- K5b: residual GEMM g_res = relu(x @ W_res + b_res) ------------
__global__ __launch_bounds__(256) void k_res(const float* __restrict__ x,
                                             const float* __restrict__ Wres,
                                             const float* __restrict__ bres) {
    __shared__ float sAT[128][36];
    int tid = threadIdx.x;
    int n0 = blockIdx.x * 32;

    for (int idx = tid; idx < 32 * 32; idx += 256) {
        int i = idx & 31, j = idx >> 5;
        float4 v = __ldg((const float4*)(x + (size_t)(n0 + i) * FIN) + j);
        int k = j << 2;
        sAT[k + 0][i] = v.x; sAT[k + 1][i] = v.y;
        sAT[k + 2][i] = v.z; sAT[k + 3][i] = v.w;
    }
    __syncthreads();

    int tx = tid & 31, ty = tid >> 5;
    const float4* W4 = (const float4*)Wres;
    float c00=0,c01=0,c02=0,c03=0, c10=0,c11=0,c12=0,c13=0;
    float c20=0,c21=0,c22=0,c23=0, c30=0,c31=0,c32=0,c33=0;

    #pragma unroll 4
    for (int k = 0; k < 128; k++) {
        float4 b = __ldg(&W4[(k << 5) + tx]);
        float4 a = *(const float4*)&sAT[k][ty << 2];
        c00 += a.x*b.x; c01 += a.x*b.y; c02 += a.x*b.z; c03 += a.x*b.w;
        c10 += a.y*b.x; c11 += a.y*b.y; c12 += a.y*b.z; c13 += a.y*b.w;
        c20 += a.z*b.x; c21 += a.z*b.y; c22 += a.z*b.z; c23 += a.z*b.w;
        c30 += a.w*b.x; c31 += a.w*b.y; c32 += a.w*b.z; c33 += a.w*b.w;
    }

    float4 br = __ldg(&((const float4*)bres)[tx]);
    float4 rows[4] = {
        make_float4(fmaxf(c00+br.x,0.f), fmaxf(c01+br.y,0.f), fmaxf(c02+br.z,0.f), fmaxf(c03+br.w,0.f)),
        make_float4(fmaxf(c10+br.x,0.f), fmaxf(c11+br.y,0.f), fmaxf(c12+br.z,0.f), fmaxf(c13+br.w,0.f)),
        make_float4(fmaxf(c20+br.x,0.f), fmaxf(c21+br.y,0.f), fmaxf(c22+br.z,0.f), fmaxf(c23+br.w,0.f)),
        make_float4(fmaxf(c30+br.x,0.f), fmaxf(c31+br.y,0.f), fmaxf(c32+br.z,0.f), fmaxf(c33+br.w,0.f))
    };
    #pragma unroll
    for (int i = 0; i < 4; i++)
        *(float4*)(g_res + (size_t)(n0 + (ty << 2) + i) * FOUT + (tx << 2)) = rows[i];
}

// ---------------- K6: segmented reduce + bias/relu + residual --------------------
__global__ __launch_bounds__(128) void k_reduce(const float* __restrict__ h_bias) {
    int n = blockIdx.x, o = threadIdx.x;
    float acc = 0.f;
    int s = g_dstart[n], e = g_dstart[n + 1];
    for (int j = s; j < e; j++)
        acc += g_edge_out[(size_t)g_dperm[j] * FOUT + o];
    acc += __ldg(&h_bias[o]);
    acc = fmaxf(acc, 0.f) + g_res[(size_t)n * FOUT + o];
    g_h[(size_t)n * FOUT + o] = acc;
}

// ---------------- K7/K8/K9: BN -----------------------------------------------------
__global__ __launch_bounds__(128) void k_bnsum() {
    int b = blockIdx.x, o = threadIdx.x;
    float s = 0.f, sq = 0.f;
    int r0 = b * (NN / NBN), r1 = r0 + (NN / NBN);
    for (int n = r0; n < r1; n++) {
        float v = g_h[(size_t)n * FOUT + o];
        s += v; sq += v * v;
    }
    g_psum[b * FOUT + o] = s;
    g_psq[b * FOUT + o] = sq;
}

__global__ __launch_bounds__(128) void k_bnfin(const float* __restrict__ gamma,
                                               const float* __restrict__ beta) {
    int o = threadIdx.x;
    float s = 0.f, sq = 0.f;
    for (int b = 0; b < NBN; b++) { s += g_psum[b * FOUT + o]; sq += g_psq[b * FOUT + o]; }
    float mean = s / (float)NN;
    float var = sq / (float)NN - mean * mean;
    float sc = gamma[o] * rsqrtf(var + 1e-5f);
    g_scale[o] = sc;
    g_shift[o] = beta[o] - mean * sc;
}

__global__ void k_out(float* __restrict__ out) {
    int i = blockIdx.x * 256 + threadIdx.x;
    if (i < NN * FOUT) {
        int o = i & 127;
        out[i] = g_h[i] * g_scale[o] + g_shift[o];
    }
}

// ---------------- launch -------------------------------------------------------------
extern "C" void kernel_launch(void* const* d_in, const int* in_sizes, int n_in,
                              void* d_out, int out_size) {
    const float* node_feats = (const float*)d_in[0];
    const int*   src        = (const int*)d_in[1];
    const int*   dst        = (const int*)d_in[2];
    const int*   etype      = (const int*)d_in[3];
    const float* norm       = (const float*)d_in[4];
    const float* basis      = (const float*)d_in[5];
    const float* comp       = (const float*)d_in[6];
    const float* h_bias     = (const float*)d_in[7];
    const float* W_res      = (const float*)d_in[8];
    const float* b_res      = (const float*)d_in[9];
    const float* gamma      = (const float*)d_in[10];
    const float* beta       = (const float*)d_in[11];
    float* out = (float*)d_out;

    const int DSMEM = 4 * ATILE;   // 139264 B
    cudaFuncSetAttribute(k_gemm, cudaFuncAttributeMaxDynamicSharedMemorySize, DSMEM);

    k_init<<<(NN + 255) / 256, 256>>>();
    k_w<<<RR * FIN, 128>>>(basis, comp);
    k_hist<<<(EE + 255) / 256, 256>>>(etype, dst);
    k_scan<<<1, 1024>>>();
    k_scatter<<<(EE + 255) / 256, 256>>>(etype, dst);
    k_gemm<<<NT_GEMM, 256, DSMEM>>>(node_feats, src, norm);
    k_res<<<NN / 32, 256>>>(node_feats, W_res, b_res);
    k_reduce<<<NN, 128>>>(h_bias);
    k_bnsum<<<NBN, 128>>>();
    k_bnfin<<<1, 128>>>(gamma, beta);
    k_out<<<(NN * FOUT + 255) / 256, 256>>>(out);
    (void)in_sizes; (void)n_in; (void)out_size;
}

// round 4
// speedup vs baseline: 2.7087x; 1.3901x over previous
#include <cuda_runtime.h>
#include <cuda_bf16.h>
#include <stdint.h>

// Problem constants
#define NN   20000
#define EE   640000
#define FIN  128
#define FOUT 128
#define RR   65
#define BB   65
#define TILE_M 128
#define NBN  100

#define ROWB 272                  // bytes per smem row (136 bf16, padded)
#define ATILE (128 * ROWB)        // 34816 B
#define GEMM_GRID 148

// ---------------- scratch (__device__ globals) ------------------------------
__device__ __align__(16) __nv_bfloat16 g_WT_hi[(size_t)RR * FOUT * FIN]; // [r][o][k]
__device__ __align__(16) __nv_bfloat16 g_WT_lo[(size_t)RR * FOUT * FIN];
__device__ __align__(16) __nv_bfloat16 g_xhi[(size_t)NN * FIN];
__device__ __align__(16) __nv_bfloat16 g_xlo[(size_t)NN * FIN];
__device__ int   g_cnt[RR];
__device__ int   g_rcur[RR];
__device__ int   g_estart[RR + 1];
__device__ int   g_tstart[RR + 1];
__device__ int   g_perm[EE];
__device__ int   g_dcnt[NN];
__device__ int   g_dcur[NN];
__device__ int   g_dstart[NN + 1];
__device__ int   g_dinv[EE];                    // edge -> dst-sorted rank
__device__ float g_edge_out[(size_t)EE * FOUT]; // indexed by dst-rank
__device__ float g_res[(size_t)NN * FOUT];
__device__ float g_h[(size_t)NN * FOUT];
__device__ float g_psum[NBN * FOUT];
__device__ float g_psq[NBN * FOUT];
__device__ float g_scale[FOUT];
__device__ float g_shift[FOUT];

// ---------------- helpers ----------------------------------------------------
__device__ __forceinline__ uint32_t smem_u32(const void* p) {
    uint32_t a;
    asm("{ .reg .u64 t; cvta.to.shared.u64 t, %1; cvt.u32.u64 %0, t; }"
        : "=r"(a) : "l"(p));
    return a;
}

__device__ __forceinline__ void ldsm_x4(uint32_t addr, uint32_t& r0, uint32_t& r1,
                                        uint32_t& r2, uint32_t& r3) {
    asm volatile("ldmatrix.sync.aligned.m8n8.x4.shared.b16 {%0,%1,%2,%3}, [%4];"
                 : "=r"(r0), "=r"(r1), "=r"(r2), "=r"(r3) : "r"(addr));
}

__device__ __forceinline__ void mma16816(float* c, const uint32_t* a,
                                         uint32_t b0, uint32_t b1) {
    asm volatile(
        "mma.sync.aligned.m16n8k16.row.col.f32.bf16.bf16.f32 "
        "{%0,%1,%2,%3}, {%4,%5,%6,%7}, {%8,%9}, {%0,%1,%2,%3};"
        : "+f"(c[0]), "+f"(c[1]), "+f"(c[2]), "+f"(c[3])
        : "r"(a[0]), "r"(a[1]), "r"(a[2]), "r"(a[3]), "r"(b0), "r"(b1));
}

__device__ __forceinline__ void cp16(uint32_t dst, const void* src, uint32_t srcsz) {
    asm volatile("cp.async.cg.shared.global [%0], [%1], 16, %2;"
                 :: "r"(dst), "l"(src), "r"(srcsz) : "memory");
}
#define CP_COMMIT() asm volatile("cp.async.commit_group;" ::: "memory")
#define CP_WAIT0()  asm volatile("cp.async.wait_group 0;" ::: "memory")

// ---------------- K0 ----------------------------------------------------------
__global__ void k_init() {
    int i = blockIdx.x * 256 + threadIdx.x;
    if (i < RR) { g_cnt[i] = 0; g_rcur[i] = 0; }
    if (i < NN) { g_dcnt[i] = 0; g_dcur[i] = 0; }
}

// ---------------- K1: WT hi/lo = (comp x basis) transposed --------------------
__global__ __launch_bounds__(128) void k_w(const float* __restrict__ basis,
                                           const float* __restrict__ comp) {
    __shared__ float sc[BB];
    int blk = blockIdx.x;          // r*128 + i
    int r = blk >> 7, i = blk & 127;
    int o = threadIdx.x;
    if (o < BB) sc[o] = comp[r * BB + o];
    __syncthreads();
    float acc = 0.f;
    const float* bp = basis + (size_t)i * FOUT + o;
    #pragma unroll 5
    for (int b = 0; b < BB; b++)
        acc += sc[b] * bp[(size_t)b * FIN * FOUT];
    __nv_bfloat16 hi = __float2bfloat16(acc);
    __nv_bfloat16 lo = __float2bfloat16(acc - __bfloat162float(hi));
    size_t tidx = ((size_t)r * FOUT + o) * FIN + i;   // [r][o][k=i]
    g_WT_hi[tidx] = hi;
    g_WT_lo[tidx] = lo;
}

// ---------------- K1b: split node feats into bf16 hi/lo -----------------------
__global__ void k_xsplit(const float* __restrict__ x) {
    int i = blockIdx.x * 256 + threadIdx.x;   // pair index
    if (i < NN * FIN / 2) {
        float2 v = ((const float2*)x)[i];
        __nv_bfloat16 h0 = __float2bfloat16(v.x);
        __nv_bfloat16 h1 = __float2bfloat16(v.y);
        __nv_bfloat16 l0 = __float2bfloat16(v.x - __bfloat162float(h0));
        __nv_bfloat16 l1 = __float2bfloat16(v.y - __bfloat162float(h1));
        ((__nv_bfloat162*)g_xhi)[i] = __nv_bfloat162(h0, h1);
        ((__nv_bfloat162*)g_xlo)[i] = __nv_bfloat162(l0, l1);
    }
}

// ---------------- K2: histograms ------------------------------------------------
__global__ void k_hist(const int* __restrict__ etype, const int* __restrict__ dst) {
    __shared__ int sh[RR];
    int tid = threadIdx.x;
    if (tid < RR) sh[tid] = 0;
    __syncthreads();
    int e = blockIdx.x * 256 + tid;
    if (e < EE) {
        atomicAdd(&sh[etype[e]], 1);
        atomicAdd(&g_dcnt[dst[e]], 1);
    }
    __syncthreads();
    if (tid < RR && sh[tid]) atomicAdd(&g_cnt[tid], sh[tid]);
}

// ---------------- K3: scans ------------------------------------------------------
__global__ __launch_bounds__(1024) void k_scan() {
    __shared__ int sp[1024];
    int t = threadIdx.x;
    int base = t * 20;
    int s = 0;
    for (int j = 0; j < 20; j++) {
        int idx = base + j;
        if (idx < NN) s += g_dcnt[idx];
    }
    sp[t] = s;
    __syncthreads();
    for (int off = 1; off < 1024; off <<= 1) {
        int v = (t >= off) ? sp[t - off] : 0;
        __syncthreads();
        sp[t] += v;
        __syncthreads();
    }
    int run = (t > 0) ? sp[t - 1] : 0;
    for (int j = 0; j < 20; j++) {
        int idx = base + j;
        if (idx < NN) { g_dstart[idx] = run; run += g_dcnt[idx]; }
    }
    if (t == 1023) g_dstart[NN] = run;
    if (t == 0) {
        int es = 0, ts = 0;
        for (int r = 0; r < RR; r++) {
            g_estart[r] = es; g_tstart[r] = ts;
            es += g_cnt[r];
            ts += (g_cnt[r] + TILE_M - 1) / TILE_M;
        }
        g_estart[RR] = es; g_tstart[RR] = ts;
    }
}

// ---------------- K4: scatter ------------------------------------------------------
__global__ void k_scatter(const int* __restrict__ etype, const int* __restrict__ dst) {
    __shared__ int s_cnt[RR], s_base[RR];
    int tid = threadIdx.x;
    if (tid < RR) s_cnt[tid] = 0;
    __syncthreads();
    int e = blockIdx.x * 256 + tid;
    bool valid = (e < EE);
    int r = 0, lrank = 0;
    if (valid) { r = etype[e]; lrank = atomicAdd(&s_cnt[r], 1); }
    __syncthreads();
    if (tid < RR && s_cnt[tid] > 0) s_base[tid] = atomicAdd(&g_rcur[tid], s_cnt[tid]);
    __syncthreads();
    if (valid) {
        g_perm[g_estart[r] + s_base[r] + lrank] = e;
        int d = dst[e];
        g_dinv[e] = g_dstart[d] + atomicAdd(&g_dcur[d], 1);
    }
}

// ---------------- K5: persistent HMMA GEMM with B reuse + A ping-pong ----------
__global__ __launch_bounds__(256) void k_gemm(const int* __restrict__ src,
                                              const float* __restrict__ norm) {
    extern __shared__ char dsm[];
    __shared__ int   s_src[2][TILE_M];
    __shared__ float s_nrm[2][TILE_M];
    __shared__ int   s_dinv[2][TILE_M];

    // smem layout: A0_hi A0_lo A1_hi A1_lo B_hi B_lo
    char* Ahi[2] = { dsm,             dsm + 2 * ATILE };
    char* Alo[2] = { dsm + ATILE,     dsm + 3 * ATILE };
    char* B_hi = dsm + 4 * ATILE;
    char* B_lo = dsm + 5 * ATILE;

    int tid = threadIdx.x;
    int T = g_tstart[RR];
    int per = (T + GEMM_GRID - 1) / GEMM_GRID;
    int t0 = blockIdx.x * per;
    int t1 = t0 + per; if (t1 > T) t1 = T;
    if (t0 >= t1) return;

    int lane = tid & 31, w = tid >> 5;
    int wm = w & 3, wn = w >> 2;
    int rm = wm * 32;
    uint32_t aLane = (uint32_t)((rm + (lane & 15)) * ROWB + ((lane >> 4) << 4));
    uint32_t bLane = (uint32_t)((wn * 64 + ((lane >> 4) << 3) + (lane & 7)) * ROWB
                                + (((lane >> 3) & 1) << 4));
    uint32_t aBaseHi[2] = { smem_u32(Ahi[0]) + aLane, smem_u32(Ahi[1]) + aLane };
    uint32_t aBaseLo[2] = { smem_u32(Alo[0]) + aLane, smem_u32(Alo[1]) + aLane };
    uint32_t bAddrHi = smem_u32(B_hi) + bLane;
    uint32_t bAddrLo = smem_u32(B_lo) + bLane;

    // relation of first tile
    int r = 0;
    while (g_tstart[r + 1] <= t0) r++;

    // ---- sync meta load for tile t0 into buf 0 ----
    {
        int ebase = g_estart[r] + (t0 - g_tstart[r]) * TILE_M;
        int cnt = g_estart[r + 1] - ebase; if (cnt > TILE_M) cnt = TILE_M;
        if (tid < TILE_M) {
            int sv = 0, dv = -1; float nm = 0.f;
            if (tid < cnt) {
                int e = g_perm[ebase + tid];
                sv = src[e]; nm = norm[e]; dv = g_dinv[e];
            }
            s_src[0][tid] = sv; s_nrm[0][tid] = nm; s_dinv[0][tid] = dv;
        }
    }
    __syncthreads();

    // ---- B fill for r + A fill for t0 (cp.async) ----
    {
        const char* WH = (const char*)g_WT_hi + (size_t)r * 32768;
        const char* WL = (const char*)g_WT_lo + (size_t)r * 32768;
        #pragma unroll
        for (int it = 0; it < 16; it++) {
            int id = tid + it * 256;
            int arr = id >> 11, o = (id >> 4) & 127, j = id & 15;
            cp16(smem_u32((arr ? B_lo : B_hi) + o * ROWB + j * 16),
                 (arr ? WL : WH) + o * 256 + j * 16, 16);
        }
        CP_COMMIT();
        #pragma unroll
        for (int it = 0; it < 16; it++) {
            int id = tid + it * 256;
            int arr = id >> 11, m = (id >> 4) & 127, j = id & 15;
            const char* gx = (const char*)(arr ? g_xlo : g_xhi)
                             + (size_t)s_src[0][m] * 256 + j * 16;
            uint32_t sz = (s_dinv[0][m] >= 0) ? 16u : 0u;
            cp16(smem_u32((arr ? Alo[0] : Ahi[0]) + m * ROWB + j * 16), gx, sz);
        }
        CP_COMMIT();
    }
    CP_WAIT0();
    __syncthreads();

    int buf = 0;
    for (int t = t0; t < t1; t++) {
        bool hasNext = (t + 1 < t1);
        int rn = r;
        if (hasNext) { while (g_tstart[rn + 1] <= t + 1) rn++; }

        // 1. prefetch meta for next tile into registers
        int m_src = 0, m_dinv = -1; float m_nrm = 0.f;
        if (hasNext && tid < TILE_M) {
            int ebase = g_estart[rn] + (t + 1 - g_tstart[rn]) * TILE_M;
            int cnt = g_estart[rn + 1] - ebase; if (cnt > TILE_M) cnt = TILE_M;
            if (tid < cnt) {
                int e = g_perm[ebase + tid];
                m_src = src[e]; m_nrm = norm[e]; m_dinv = g_dinv[e];
            }
        }

        float acc[2][8][4];
        #pragma unroll
        for (int a = 0; a < 2; a++)
            #pragma unroll
            for (int b = 0; b < 8; b++)
                #pragma unroll
                for (int c = 0; c < 4; c++) acc[a][b][c] = 0.f;

        // 2. product 0: Ah * Bh (hides meta LDG latency)
        {
            uint32_t aA = aBaseHi[buf];
            #pragma unroll
            for (int s = 0; s < 8; s++) {
                uint32_t ka = aA + s * 32, kb = bAddrHi + s * 32;
                uint32_t a0[4], a1[4];
                ldsm_x4(ka,             a0[0], a0[1], a0[2], a0[3]);
                ldsm_x4(ka + 16 * ROWB, a1[0], a1[1], a1[2], a1[3]);
                #pragma unroll
                for (int pr = 0; pr < 4; pr++) {
                    uint32_t b0, b1, b2, b3;
                    ldsm_x4(kb + pr * 16 * ROWB, b0, b1, b2, b3);
                    int nt = pr * 2;
                    mma16816(acc[0][nt],     a0, b0, b1);
                    mma16816(acc[1][nt],     a1, b0, b1);
                    mma16816(acc[0][nt + 1], a0, b2, b3);
                    mma16816(acc[1][nt + 1], a1, b2, b3);
                }
            }
        }

        // 3. publish next meta
        if (hasNext && tid < TILE_M) {
            s_src[buf ^ 1][tid] = m_src;
            s_nrm[buf ^ 1][tid] = m_nrm;
            s_dinv[buf ^ 1][tid] = m_dinv;
        }
        __syncthreads();

        // 4. issue A prefetch for next tile
        if (hasNext) {
            int nb = buf ^ 1;
            #pragma unroll
            for (int it = 0; it < 16; it++) {
                int id = tid + it * 256;
                int arr = id >> 11, m = (id >> 4) & 127, j = id & 15;
                const char* gx = (const char*)(arr ? g_xlo : g_xhi)
                                 + (size_t)s_src[nb][m] * 256 + j * 16;
                uint32_t sz = (s_dinv[nb][m] >= 0) ? 16u : 0u;
                cp16(smem_u32((arr ? Alo[nb] : Ahi[nb]) + m * ROWB + j * 16), gx, sz);
            }
            CP_COMMIT();
        }

        // 5. products 1 and 2 (hide A prefetch latency)
        #pragma unroll 1
        for (int p = 1; p < 3; p++) {
            uint32_t aA = (p == 1) ? aBaseLo[buf] : aBaseHi[buf];
            uint32_t bA = (p == 1) ? bAddrHi : bAddrLo;
            #pragma unroll
            for (int s = 0; s < 8; s++) {
                uint32_t ka = aA + s * 32, kb = bA + s * 32;
                uint32_t a0[4], a1[4];
                ldsm_x4(ka,             a0[0], a0[1], a0[2], a0[3]);
                ldsm_x4(ka + 16 * ROWB, a1[0], a1[1], a1[2], a1[3]);
                #pragma unroll
                for (int pr = 0; pr < 4; pr++) {
                    uint32_t b0, b1, b2, b3;
                    ldsm_x4(kb + pr * 16 * ROWB, b0, b1, b2, b3);
                    int nt = pr * 2;
                    mma16816(acc[0][nt],     a0, b0, b1);
                    mma16816(acc[1][nt],     a1, b0, b1);
                    mma16816(acc[0][nt + 1], a0, b2, b3);
                    mma16816(acc[1][nt + 1], a1, b2, b3);
                }
            }
        }

        // 6. epilogue: scale by norm, write rows at dst-rank
        {
            int colBase = wn * 64 + (lane & 3) * 2;
            #pragma unroll
            for (int mt = 0; mt < 2; mt++) {
                int row0 = rm + mt * 16 + (lane >> 2);
                int d0 = s_dinv[buf][row0], d1 = s_dinv[buf][row0 + 8];
                float n0 = s_nrm[buf][row0], n1 = s_nrm[buf][row0 + 8];
                float* p0 = (d0 >= 0) ? g_edge_out + (size_t)d0 * FOUT + colBase : (float*)0;
                float* p1 = (d1 >= 0) ? g_edge_out + (size_t)d1 * FOUT + colBase : (float*)0;
                #pragma unroll
                for (int nt = 0; nt < 8; nt++) {
                    if (p0) *(float2*)(p0 + nt * 8) =
                        make_float2(acc[mt][nt][0] * n0, acc[mt][nt][1] * n0);
                    if (p1) *(float2*)(p1 + nt * 8) =
                        make_float2(acc[mt][nt][2] * n1, acc[mt][nt][3] * n1);
                }
            }
        }

        // 7. B reload if relation changes (rare)
        if (hasNext) {
            if (rn != r) {
                CP_WAIT0();
                __syncthreads();
                const char* WH = (const char*)g_WT_hi + (size_t)rn * 32768;
                const char* WL = (const char*)g_WT_lo + (size_t)rn * 32768;
                #pragma unroll
                for (int it = 0; it < 16; it++) {
                    int id = tid + it * 256;
                    int arr = id >> 11, o = (id >> 4) & 127, j = id & 15;
                    cp16(smem_u32((arr ? B_lo : B_hi) + o * ROWB + j * 16),
                         (arr ? WL : WH) + o * 256 + j * 16, 16);
                }
                CP_COMMIT();
                r = rn;
            }
            CP_WAIT0();
            __syncthreads();
        }
        buf ^= 1;
    }
}

// ---------------- K5b: residual GEMM g_res = relu(x @ W_res + b_res) ------------
__global__ __launch_bounds__(256) void k_res(const float* __restrict__ x,
                                             const float* __restrict__ Wres,
                                             const float* __restrict__ bres) {
    __shared__ float sAT[128][36];
    int tid = threadIdx.x;
    int n0 = blockIdx.x * 32;

    for (int idx = tid; idx < 32 * 32; idx += 256) {
        int i = idx & 31, j = idx >> 5;
        float4 v = __ldg((const float4*)(x + (size_t)(n0 + i) * FIN) + j);
        int k = j << 2;
        sAT[k + 0][i] = v.x; sAT[k + 1][i] = v.y;
        sAT[k + 2][i] = v.z; sAT[k + 3][i] = v.w;
    }
    __syncthreads();

    int tx = tid & 31, ty = tid >> 5;
    const float4* W4 = (const float4*)Wres;
    float c00=0,c01=0,c02=0,c03=0, c10=0,c11=0,c12=0,c13=0;
    float c20=0,c21=0,c22=0,c23=0, c30=0,c31=0,c32=0,c33=0;

    #pragma unroll 4
    for (int k = 0; k < 128; k++) {
        float4 b = __ldg(&W4[(k << 5) + tx]);
        float4 a = *(const float4*)&sAT[k][ty << 2];
        c00 += a.x*b.x; c01 += a.x*b.y; c02 += a.x*b.z; c03 += a.x*b.w;
        c10 += a.y*b.x; c11 += a.y*b.y; c12 += a.y*b.z; c13 += a.y*b.w;
        c20 += a.z*b.x; c21 += a.z*b.y; c22 += a.z*b.z; c23 += a.z*b.w;
        c30 += a.w*b.x; c31 += a.w*b.y; c32 += a.w*b.z; c33 += a.w*b.w;
    }

    float4 br = __ldg(&((const float4*)bres)[tx]);
    float4 rows[4] = {
        make_float4(fmaxf(c00+br.x,0.f), fmaxf(c01+br.y,0.f), fmaxf(c02+br.z,0.f), fmaxf(c03+br.w,0.f)),
        make_float4(fmaxf(c10+br.x,0.f), fmaxf(c11+br.y,0.f), fmaxf(c12+br.z,0.f), fmaxf(c13+br.w,0.f)),
        make_float4(fmaxf(c20+br.x,0.f), fmaxf(c21+br.y,0.f), fmaxf(c22+br.z,0.f), fmaxf(c23+br.w,0.f)),
        make_float4(fmaxf(c30+br.x,0.f), fmaxf(c31+br.y,0.f), fmaxf(c32+br.z,0.f), fmaxf(c33+br.w,0.f))
    };
    #pragma unroll
    for (int i = 0; i < 4; i++)
        *(float4*)(g_res + (size_t)(n0 + (ty << 2) + i) * FOUT + (tx << 2)) = rows[i];
}

// ---------------- K6: segmented reduce (sequential stream) + relu + residual -----
__global__ __launch_bounds__(128) void k_reduce(const float* __restrict__ h_bias) {
    int n = blockIdx.x, o = threadIdx.x;
    float acc = 0.f;
    int s = g_dstart[n], e = g_dstart[n + 1];
    const float* p = g_edge_out + (size_t)s * FOUT + o;
    for (int j = s; j < e; j++, p += FOUT)
        acc += *p;
    acc += __ldg(&h_bias[o]);
    acc = fmaxf(acc, 0.f) + g_res[(size_t)n * FOUT + o];
    g_h[(size_t)n * FOUT + o] = acc;
}

// ---------------- K7/K8/K9: BN -----------------------------------------------------
__global__ __launch_bounds__(128) void k_bnsum() {
    int b = blockIdx.x, o = threadIdx.x;
    float s = 0.f, sq = 0.f;
    int r0 = b * (NN / NBN), r1 = r0 + (NN / NBN);
    for (int n = r0; n < r1; n++) {
        float v = g_h[(size_t)n * FOUT + o];
        s += v; sq += v * v;
    }
    g_psum[b * FOUT + o] = s;
    g_psq[b * FOUT + o] = sq;
}

__global__ __launch_bounds__(128) void k_bnfin(const float* __restrict__ gamma,
                                               const float* __restrict__ beta) {
    int o = threadIdx.x;
    float s = 0.f, sq = 0.f;
    for (int b = 0; b < NBN; b++) { s += g_psum[b * FOUT + o]; sq += g_psq[b * FOUT + o]; }
    float mean = s / (float)NN;
    float var = sq / (float)NN - mean * mean;
    float sc = gamma[o] * rsqrtf(var + 1e-5f);
    g_scale[o] = sc;
    g_shift[o] = beta[o] - mean * sc;
}

__global__ void k_out(float* __restrict__ out) {
    int i = blockIdx.x * 256 + threadIdx.x;
    if (i < NN * FOUT) {
        int o = i & 127;
        out[i] = g_h[i] * g_scale[o] + g_shift[o];
    }
}

// ---------------- launch -------------------------------------------------------------
extern "C" void kernel_launch(void* const* d_in, const int* in_sizes, int n_in,
                              void* d_out, int out_size) {
    const float* node_feats = (const float*)d_in[0];
    const int*   src        = (const int*)d_in[1];
    const int*   dst        = (const int*)d_in[2];
    const int*   etype      = (const int*)d_in[3];
    const float* norm       = (const float*)d_in[4];
    const float* basis      = (const float*)d_in[5];
    const float* comp       = (const float*)d_in[6];
    const float* h_bias     = (const float*)d_in[7];
    const float* W_res      = (const float*)d_in[8];
    const float* b_res      = (const float*)d_in[9];
    const float* gamma      = (const float*)d_in[10];
    const float* beta       = (const float*)d_in[11];
    float* out = (float*)d_out;

    const int DSMEM = 6 * ATILE;   // 208896 B: A ping-pong hi/lo + B hi/lo
    cudaFuncSetAttribute(k_gemm, cudaFuncAttributeMaxDynamicSharedMemorySize, DSMEM);

    k_init<<<(NN + 255) / 256, 256>>>();
    k_w<<<RR * FIN, 128>>>(basis, comp);
    k_xsplit<<<(NN * FIN / 2 + 255) / 256, 256>>>(node_feats);
    k_hist<<<(EE + 255) / 256, 256>>>(etype, dst);
    k_scan<<<1, 1024>>>();
    k_scatter<<<(EE + 255) / 256, 256>>>(etype, dst);
    k_gemm<<<GEMM_GRID, 256, DSMEM>>>(src, norm);
    k_res<<<NN / 32, 256>>>(node_feats, W_res, b_res);
    k_reduce<<<NN, 128>>>(h_bias);
    k_bnsum<<<NBN, 128>>>();
    k_bnfin<<<1, 128>>>(gamma, beta);
    k_out<<<(NN * FOUT + 255) / 256, 256>>>(out);
    (void)in_sizes; (void)n_in; (void)out_size;
}

// round 5
// speedup vs baseline: 3.4795x; 1.2846x over previous
#include <cuda_runtime.h>
#include <cuda_fp16.h>
#include <stdint.h>

// Problem constants
#define NN   20000
#define EE   640000
#define FIN  128
#define FOUT 128
#define RR   65
#define BB   65
#define TILE_M 128
#define NBN  100

#define ROWB 272                  // bytes per smem tile row (136 halves, padded)
#define ATILE (128 * ROWB)        // 34816 B
#define GEMM_GRID 148

// ---------------- scratch (__device__ globals) ------------------------------
__device__ __align__(16) __half g_WT_hi[(size_t)RR * FOUT * FIN]; // [r][o][k]
__device__ __align__(16) __half g_WT_lo[(size_t)RR * FOUT * FIN];
__device__ __align__(16) __half g_xh[(size_t)NN * FIN];
__device__ int   g_cnt[RR];
__device__ int   g_rcur[RR];
__device__ int   g_estart[RR + 1];
__device__ int   g_tstart[RR + 1];
__device__ int   g_perm[EE];
__device__ int   g_dcnt[NN];
__device__ int   g_dcur[NN];
__device__ int   g_dstart[NN + 1];
__device__ int   g_dinv[EE];                     // edge -> dst-sorted rank
__device__ __align__(16) __half g_edge_out[(size_t)EE * FOUT]; // dst-rank order
__device__ float g_res[(size_t)NN * FOUT];
__device__ float g_h[(size_t)NN * FOUT];
__device__ float g_psum[NBN * FOUT];
__device__ float g_psq[NBN * FOUT];
__device__ float g_scale[FOUT];
__device__ float g_shift[FOUT];

// ---------------- helpers ----------------------------------------------------
__device__ __forceinline__ uint32_t smem_u32(const void* p) {
    uint32_t a;
    asm("{ .reg .u64 t; cvta.to.shared.u64 t, %1; cvt.u32.u64 %0, t; }"
        : "=r"(a) : "l"(p));
    return a;
}

__device__ __forceinline__ void ldsm_x4(uint32_t addr, uint32_t& r0, uint32_t& r1,
                                        uint32_t& r2, uint32_t& r3) {
    asm volatile("ldmatrix.sync.aligned.m8n8.x4.shared.b16 {%0,%1,%2,%3}, [%4];"
                 : "=r"(r0), "=r"(r1), "=r"(r2), "=r"(r3) : "r"(addr));
}

__device__ __forceinline__ void mma16816(float* c, const uint32_t* a,
                                         uint32_t b0, uint32_t b1) {
    asm volatile(
        "mma.sync.aligned.m16n8k16.row.col.f32.f16.f16.f32 "
        "{%0,%1,%2,%3}, {%4,%5,%6,%7}, {%8,%9}, {%0,%1,%2,%3};"
        : "+f"(c[0]), "+f"(c[1]), "+f"(c[2]), "+f"(c[3])
        : "r"(a[0]), "r"(a[1]), "r"(a[2]), "r"(a[3]), "r"(b0), "r"(b1));
}

__device__ __forceinline__ void cp16(uint32_t dst, const void* src) {
    asm volatile("cp.async.cg.shared.global [%0], [%1], 16;"
                 :: "r"(dst), "l"(src) : "memory");
}
#define CP_COMMIT() asm volatile("cp.async.commit_group;" ::: "memory")
#define CP_WAIT0()  asm volatile("cp.async.wait_group 0;" ::: "memory")

// ---------------- K1: WT hi/lo fp16 = (comp x basis) transposed ---------------
__global__ __launch_bounds__(128) void k_w(const float* __restrict__ basis,
                                           const float* __restrict__ comp) {
    __shared__ float sc[BB];
    int blk = blockIdx.x;          // r*128 + i
    int r = blk >> 7, i = blk & 127;
    int o = threadIdx.x;
    if (o < BB) sc[o] = comp[r * BB + o];
    __syncthreads();
    float acc = 0.f;
    const float* bp = basis + (size_t)i * FOUT + o;
    #pragma unroll 5
    for (int b = 0; b < BB; b++)
        acc += sc[b] * bp[(size_t)b * FIN * FOUT];
    __half hi = __float2half(acc);
    __half lo = __float2half(acc - __half2float(hi));
    size_t tidx = ((size_t)r * FOUT + o) * FIN + i;   // [r][o][k=i]
    g_WT_hi[tidx] = hi;
    g_WT_lo[tidx] = lo;
}

// ---------------- K1b: x -> fp16; also zero counters ---------------------------
__global__ void k_xcvt(const float* __restrict__ x) {
    int i = blockIdx.x * 256 + threadIdx.x;          // half2 index
    if (i < NN * FIN / 2) {
        float2 v = ((const float2*)x)[i];
        ((__half2*)g_xh)[i] = __floats2half2_rn(v.x, v.y);
    }
    if (i < NN) { g_dcnt[i] = 0; g_dcur[i] = 0; }
    if (i < RR) { g_cnt[i] = 0; g_rcur[i] = 0; }
}

// ---------------- K2: histograms ------------------------------------------------
__global__ void k_hist(const int* __restrict__ etype, const int* __restrict__ dst) {
    __shared__ int sh[RR];
    int tid = threadIdx.x;
    if (tid < RR) sh[tid] = 0;
    __syncthreads();
    int e = blockIdx.x * 256 + tid;
    if (e < EE) {
        atomicAdd(&sh[etype[e]], 1);
        atomicAdd(&g_dcnt[dst[e]], 1);
    }
    __syncthreads();
    if (tid < RR && sh[tid]) atomicAdd(&g_cnt[tid], sh[tid]);
}

// ---------------- K3: scans (dst counts staged through smem) --------------------
__global__ __launch_bounds__(1024) void k_scan() {
    extern __shared__ int sdc[];   // 20000 ints
    __shared__ int sp[1024];
    int t = threadIdx.x;

    // coalesced stage-in
    for (int i = t; i < NN / 4; i += 1024)
        ((int4*)sdc)[i] = ((const int4*)g_dcnt)[i];
    __syncthreads();

    int base = t * 20;
    int s = 0;
    #pragma unroll
    for (int j = 0; j < 20; j++) {
        int idx = base + j;
        if (idx < NN) s += sdc[idx];
    }
    sp[t] = s;
    __syncthreads();
    for (int off = 1; off < 1024; off <<= 1) {
        int v = (t >= off) ? sp[t - off] : 0;
        __syncthreads();
        sp[t] += v;
        __syncthreads();
    }
    int run = (t > 0) ? sp[t - 1] : 0;
    #pragma unroll
    for (int j = 0; j < 20; j++) {
        int idx = base + j;
        if (idx < NN) { g_dstart[idx] = run; run += sdc[idx]; }
    }
    if (t == 1023) g_dstart[NN] = run;
    if (t == 0) {
        int es = 0, ts = 0;
        for (int r = 0; r < RR; r++) {
            g_estart[r] = es; g_tstart[r] = ts;
            es += g_cnt[r];
            ts += (g_cnt[r] + TILE_M - 1) / TILE_M;
        }
        g_estart[RR] = es; g_tstart[RR] = ts;
    }
}

// ---------------- K4: scatter ------------------------------------------------------
__global__ void k_scatter(const int* __restrict__ etype, const int* __restrict__ dst) {
    __shared__ int s_cnt[RR], s_base[RR];
    int tid = threadIdx.x;
    if (tid < RR) s_cnt[tid] = 0;
    __syncthreads();
    int e = blockIdx.x * 256 + tid;
    bool valid = (e < EE);
    int r = 0, lrank = 0;
    if (valid) { r = etype[e]; lrank = atomicAdd(&s_cnt[r], 1); }
    __syncthreads();
    if (tid < RR && s_cnt[tid] > 0) s_base[tid] = atomicAdd(&g_rcur[tid], s_cnt[tid]);
    __syncthreads();
    if (valid) {
        g_perm[g_estart[r] + s_base[r] + lrank] = e;
        int d = dst[e];
        g_dinv[e] = g_dstart[d] + atomicAdd(&g_dcur[d], 1);
    }
}

// ---------------- K5: persistent HMMA GEMM: A=fp16(x), B=W hi/lo, 2 products -----
__global__ __launch_bounds__(256) void k_gemm(const int* __restrict__ src,
                                              const float* __restrict__ norm) {
    extern __shared__ char dsm[];
    __shared__ int   s_src[2][TILE_M];
    __shared__ float s_nrm[2][TILE_M];
    __shared__ int   s_dinv[2][TILE_M];

    // smem: A0 A1 B_hi B_lo
    char* Abuf[2] = { dsm, dsm + ATILE };
    char* B_hi = dsm + 2 * ATILE;
    char* B_lo = dsm + 3 * ATILE;

    int tid = threadIdx.x;
    int T = g_tstart[RR];
    int per = (T + GEMM_GRID - 1) / GEMM_GRID;
    int t0 = blockIdx.x * per;
    int t1 = t0 + per; if (t1 > T) t1 = T;
    if (t0 >= t1) return;

    int lane = tid & 31, w = tid >> 5;
    int wm = w & 3, wn = w >> 2;
    int rm = wm * 32;
    uint32_t aLane = (uint32_t)((rm + (lane & 15)) * ROWB + ((lane >> 4) << 4));
    uint32_t bLane = (uint32_t)((wn * 64 + ((lane >> 4) << 3) + (lane & 7)) * ROWB
                                + (((lane >> 3) & 1) << 4));
    uint32_t aBase[2] = { smem_u32(Abuf[0]) + aLane, smem_u32(Abuf[1]) + aLane };
    uint32_t bAddrHi = smem_u32(B_hi) + bLane;
    uint32_t bAddrLo = smem_u32(B_lo) + bLane;

    int r = 0;
    while (g_tstart[r + 1] <= t0) r++;

    // ---- sync meta for tile t0 (buf 0) ----
    {
        int ebase = g_estart[r] + (t0 - g_tstart[r]) * TILE_M;
        int cnt = g_estart[r + 1] - ebase; if (cnt > TILE_M) cnt = TILE_M;
        if (tid < TILE_M) {
            int sv = 0, dv = -1; float nm = 0.f;
            if (tid < cnt) {
                int e = g_perm[ebase + tid];
                sv = src[e]; nm = norm[e]; dv = g_dinv[e];
            }
            s_src[0][tid] = sv; s_nrm[0][tid] = nm; s_dinv[0][tid] = dv;
        }
    }
    __syncthreads();

    // ---- B (hi+lo) fill for r, A fill for t0 ----
    {
        const char* WH = (const char*)g_WT_hi + (size_t)r * 32768;
        const char* WL = (const char*)g_WT_lo + (size_t)r * 32768;
        #pragma unroll
        for (int it = 0; it < 16; it++) {
            int id = tid + it * 256;
            int arr = id >> 11, o = (id >> 4) & 127, j = id & 15;
            cp16(smem_u32((arr ? B_lo : B_hi) + o * ROWB + j * 16),
                 (arr ? WL : WH) + o * 256 + j * 16);
        }
        #pragma unroll
        for (int it = 0; it < 8; it++) {
            int id = tid + it * 256;
            int m = id >> 4, j = id & 15;
            cp16(smem_u32(Abuf[0] + m * ROWB + j * 16),
                 (const char*)g_xh + (size_t)s_src[0][m] * 256 + j * 16);
        }
        CP_COMMIT();
    }
    CP_WAIT0();
    __syncthreads();

    int buf = 0;
    for (int t = t0; t < t1; t++) {
        bool hasNext = (t + 1 < t1);
        int rn = r;
        if (hasNext) { while (g_tstart[rn + 1] <= t + 1) rn++; }

        // 1. meta prefetch for next tile (registers)
        int m_src = 0, m_dinv = -1; float m_nrm = 0.f;
        if (hasNext && tid < TILE_M) {
            int ebase = g_estart[rn] + (t + 1 - g_tstart[rn]) * TILE_M;
            int cnt = g_estart[rn + 1] - ebase; if (cnt > TILE_M) cnt = TILE_M;
            if (tid < cnt) {
                int e = g_perm[ebase + tid];
                m_src = src[e]; m_nrm = norm[e]; m_dinv = g_dinv[e];
            }
        }

        float acc[2][8][4];
        #pragma unroll
        for (int a = 0; a < 2; a++)
            #pragma unroll
            for (int b = 0; b < 8; b++)
                #pragma unroll
                for (int c = 0; c < 4; c++) acc[a][b][c] = 0.f;

        // 2. product 0: A * B_hi (hides meta LDG)
        {
            uint32_t aA = aBase[buf];
            #pragma unroll
            for (int s = 0; s < 8; s++) {
                uint32_t ka = aA + s * 32, kb = bAddrHi + s * 32;
                uint32_t a0[4], a1[4];
                ldsm_x4(ka,             a0[0], a0[1], a0[2], a0[3]);
                ldsm_x4(ka + 16 * ROWB, a1[0], a1[1], a1[2], a1[3]);
                #pragma unroll
                for (int pr = 0; pr < 4; pr++) {
                    uint32_t b0, b1, b2, b3;
                    ldsm_x4(kb + pr * 16 * ROWB, b0, b1, b2, b3);
                    int nt = pr * 2;
                    mma16816(acc[0][nt],     a0, b0, b1);
                    mma16816(acc[1][nt],     a1, b0, b1);
                    mma16816(acc[0][nt + 1], a0, b2, b3);
                    mma16816(acc[1][nt + 1], a1, b2, b3);
                }
            }
        }

        // 3. publish next meta
        if (hasNext && tid < TILE_M) {
            s_src[buf ^ 1][tid] = m_src;
            s_nrm[buf ^ 1][tid] = m_nrm;
            s_dinv[buf ^ 1][tid] = m_dinv;
        }
        __syncthreads();

        // 4. A prefetch for next tile
        if (hasNext) {
            int nb = buf ^ 1;
            #pragma unroll
            for (int it = 0; it < 8; it++) {
                int id = tid + it * 256;
                int m = id >> 4, j = id & 15;
                cp16(smem_u32(Abuf[nb] + m * ROWB + j * 16),
                     (const char*)g_xh + (size_t)s_src[nb][m] * 256 + j * 16);
            }
            CP_COMMIT();
        }

        // 5. product 1: A * B_lo (hides A prefetch)
        {
            uint32_t aA = aBase[buf];
            #pragma unroll
            for (int s = 0; s < 8; s++) {
                uint32_t ka = aA + s * 32, kb = bAddrLo + s * 32;
                uint32_t a0[4], a1[4];
                ldsm_x4(ka,             a0[0], a0[1], a0[2], a0[3]);
                ldsm_x4(ka + 16 * ROWB, a1[0], a1[1], a1[2], a1[3]);
                #pragma unroll
                for (int pr = 0; pr < 4; pr++) {
                    uint32_t b0, b1, b2, b3;
                    ldsm_x4(kb + pr * 16 * ROWB, b0, b1, b2, b3);
                    int nt = pr * 2;
                    mma16816(acc[0][nt],     a0, b0, b1);
                    mma16816(acc[1][nt],     a1, b0, b1);
                    mma16816(acc[0][nt + 1], a0, b2, b3);
                    mma16816(acc[1][nt + 1], a1, b2, b3);
                }
            }
        }

        // 6. epilogue: scale by norm, store fp16 rows at dst-rank
        {
            int colBase = wn * 64 + (lane & 3) * 2;
            #pragma unroll
            for (int mt = 0; mt < 2; mt++) {
                int row0 = rm + mt * 16 + (lane >> 2);
                int d0 = s_dinv[buf][row0], d1 = s_dinv[buf][row0 + 8];
                float n0 = s_nrm[buf][row0], n1 = s_nrm[buf][row0 + 8];
                __half* p0 = (d0 >= 0) ? g_edge_out + (size_t)d0 * FOUT + colBase : (__half*)0;
                __half* p1 = (d1 >= 0) ? g_edge_out + (size_t)d1 * FOUT + colBase : (__half*)0;
                #pragma unroll
                for (int nt = 0; nt < 8; nt++) {
                    if (p0) *(__half2*)(p0 + nt * 8) =
                        __floats2half2_rn(acc[mt][nt][0] * n0, acc[mt][nt][1] * n0);
                    if (p1) *(__half2*)(p1 + nt * 8) =
                        __floats2half2_rn(acc[mt][nt][2] * n1, acc[mt][nt][3] * n1);
                }
            }
        }

        // 7. B reload on relation change
        if (hasNext) {
            if (rn != r) {
                CP_WAIT0();
                __syncthreads();
                const char* WH = (const char*)g_WT_hi + (size_t)rn * 32768;
                const char* WL = (const char*)g_WT_lo + (size_t)rn * 32768;
                #pragma unroll
                for (int it = 0; it < 16; it++) {
                    int id = tid + it * 256;
                    int arr = id >> 11, o = (id >> 4) & 127, j = id & 15;
                    cp16(smem_u32((arr ? B_lo : B_hi) + o * ROWB + j * 16),
                         (arr ? WL : WH) + o * 256 + j * 16);
                }
                CP_COMMIT();
                r = rn;
            }
            CP_WAIT0();
            __syncthreads();
        }
        buf ^= 1;
    }
}

// ---------------- K5b: residual GEMM g_res = relu(x @ W_res + b_res) ------------
__global__ __launch_bounds__(256) void k_res(const float* __restrict__ x,
                                             const float* __restrict__ Wres,
                                             const float* __restrict__ bres) {
    __shared__ float sAT[128][36];
    int tid = threadIdx.x;
    int n0 = blockIdx.x * 32;

    for (int idx = tid; idx < 32 * 32; idx += 256) {
        int i = idx & 31, j = idx >> 5;
        float4 v = __ldg((const float4*)(x + (size_t)(n0 + i) * FIN) + j);
        int k = j << 2;
        sAT[k + 0][i] = v.x; sAT[k + 1][i] = v.y;
        sAT[k + 2][i] = v.z; sAT[k + 3][i] = v.w;
    }
    __syncthreads();

    int tx = tid & 31, ty = tid >> 5;
    const float4* W4 = (const float4*)Wres;
    float c00=0,c01=0,c02=0,c03=0, c10=0,c11=0,c12=0,c13=0;
    float c20=0,c21=0,c22=0,c23=0, c30=0,c31=0,c32=0,c33=0;

    #pragma unroll 4
    for (int k = 0; k < 128; k++) {
        float4 b = __ldg(&W4[(k << 5) + tx]);
        float4 a = *(const float4*)&sAT[k][ty << 2];
        c00 += a.x*b.x; c01 += a.x*b.y; c02 += a.x*b.z; c03 += a.x*b.w;
        c10 += a.y*b.x; c11 += a.y*b.y; c12 += a.y*b.z; c13 += a.y*b.w;
        c20 += a.z*b.x; c21 += a.z*b.y; c22 += a.z*b.z; c23 += a.z*b.w;
        c30 += a.w*b.x; c31 += a.w*b.y; c32 += a.w*b.z; c33 += a.w*b.w;
    }

    float4 br = __ldg(&((const float4*)bres)[tx]);
    float4 rows[4] = {
        make_float4(fmaxf(c00+br.x,0.f), fmaxf(c01+br.y,0.f), fmaxf(c02+br.z,0.f), fmaxf(c03+br.w,0.f)),
        make_float4(fmaxf(c10+br.x,0.f), fmaxf(c11+br.y,0.f), fmaxf(c12+br.z,0.f), fmaxf(c13+br.w,0.f)),
        make_float4(fmaxf(c20+br.x,0.f), fmaxf(c21+br.y,0.f), fmaxf(c22+br.z,0.f), fmaxf(c23+br.w,0.f)),
        make_float4(fmaxf(c30+br.x,0.f), fmaxf(c31+br.y,0.f), fmaxf(c32+br.z,0.f), fmaxf(c33+br.w,0.f))
    };
    #pragma unroll
    for (int i = 0; i < 4; i++)
        *(float4*)(g_res + (size_t)(n0 + (ty << 2) + i) * FOUT + (tx << 2)) = rows[i];
}

// ---------------- K6: segmented reduce (half2 stream) + relu + residual ----------
// Block = 128 threads = 2 nodes x 64 lanes; lane covers 2 output cols via half2.
__global__ __launch_bounds__(128) void k_reduce(const float* __restrict__ h_bias) {
    int n = blockIdx.x * 2 + (threadIdx.x >> 6);
    int c = threadIdx.x & 63;             // half2 column
    int s = g_dstart[n], e = g_dstart[n + 1];
    float2 acc = make_float2(0.f, 0.f);
    const __half2* p = (const __half2*)g_edge_out + (size_t)s * 64 + c;
    for (int j = s; j < e; j++, p += 64) {
        float2 f = __half22float2(*p);
        acc.x += f.x; acc.y += f.y;
    }
    float2 bv = __ldg(&((const float2*)h_bias)[c]);
    acc.x = fmaxf(acc.x + bv.x, 0.f);
    acc.y = fmaxf(acc.y + bv.y, 0.f);
    float2 rv = ((const float2*)g_res)[(size_t)n * 64 + c];
    acc.x += rv.x; acc.y += rv.y;
    ((float2*)g_h)[(size_t)n * 64 + c] = acc;
}

// ---------------- K7/K8/K9: BN -----------------------------------------------------
__global__ __launch_bounds__(128) void k_bnsum() {
    int b = blockIdx.x, o = threadIdx.x;
    float s = 0.f, sq = 0.f;
    int r0 = b * (NN / NBN), r1 = r0 + (NN / NBN);
    for (int n = r0; n < r1; n++) {
        float v = g_h[(size_t)n * FOUT + o];
        s += v; sq += v * v;
    }
    g_psum[b * FOUT + o] = s;
    g_psq[b * FOUT + o] = sq;
}

__global__ __launch_bounds__(128) void k_bnfin(const float* __restrict__ gamma,
                                               const float* __restrict__ beta) {
    int o = threadIdx.x;
    float s = 0.f, sq = 0.f;
    for (int b = 0; b < NBN; b++) { s += g_psum[b * FOUT + o]; sq += g_psq[b * FOUT + o]; }
    float mean = s / (float)NN;
    float var = sq / (float)NN - mean * mean;
    float sc = gamma[o] * rsqrtf(var + 1e-5f);
    g_scale[o] = sc;
    g_shift[o] = beta[o] - mean * sc;
}

__global__ void k_out(float* __restrict__ out) {
    int i = blockIdx.x * 256 + threadIdx.x;
    if (i < NN * FOUT) {
        int o = i & 127;
        out[i] = g_h[i] * g_scale[o] + g_shift[o];
    }
}

// ---------------- launch -------------------------------------------------------------
extern "C" void kernel_launch(void* const* d_in, const int* in_sizes, int n_in,
                              void* d_out, int out_size) {
    const float* node_feats = (const float*)d_in[0];
    const int*   src        = (const int*)d_in[1];
    const int*   dst        = (const int*)d_in[2];
    const int*   etype      = (const int*)d_in[3];
    const float* norm       = (const float*)d_in[4];
    const float* basis      = (const float*)d_in[5];
    const float* comp       = (const float*)d_in[6];
    const float* h_bias     = (const float*)d_in[7];
    const float* W_res      = (const float*)d_in[8];
    const float* b_res      = (const float*)d_in[9];
    const float* gamma      = (const float*)d_in[10];
    const float* beta       = (const float*)d_in[11];
    float* out = (float*)d_out;

    const int DSMEM = 4 * ATILE;          // 139264 B: A ping-pong + B hi/lo
    const int SCAN_SMEM = NN * 4;          // 80000 B
    cudaFuncSetAttribute(k_gemm, cudaFuncAttributeMaxDynamicSharedMemorySize, DSMEM);
    cudaFuncSetAttribute(k_scan, cudaFuncAttributeMaxDynamicSharedMemorySize, SCAN_SMEM);

    k_w<<<RR * FIN, 128>>>(basis, comp);
    k_xcvt<<<(NN * FIN / 2 + 255) / 256, 256>>>(node_feats);
    k_hist<<<(EE + 255) / 256, 256>>>(etype, dst);
    k_scan<<<1, 1024, SCAN_SMEM>>>();
    k_scatter<<<(EE + 255) / 256, 256>>>(etype, dst);
    k_gemm<<<GEMM_GRID, 256, DSMEM>>>(src, norm);
    k_res<<<NN / 32, 256>>>(node_feats, W_res, b_res);
    k_reduce<<<NN / 2, 128>>>(h_bias);
    k_bnsum<<<NBN, 128>>>();
    k_bnfin<<<1, 128>>>(gamma, beta);
    k_out<<<(NN * FOUT + 255) / 256, 256>>>(out);
    (void)in_sizes; (void)n_in; (void)out_size;
}

// round 6
// speedup vs baseline: 3.4858x; 1.0018x over previous
#include <cuda_runtime.h>
#include <cuda_fp16.h>
#include <stdint.h>

// Problem constants
#define NN   20000
#define EE   640000
#define FIN  128
#define FOUT 128
#define RR   65
#define BB   65
#define TILE_M 128
#define NBN  100

#define ROWB 272                  // bytes per smem tile row (136 halves, padded)
#define ATILE (128 * ROWB)        // 34816 B
#define GEMM_GRID 148

// ---------------- scratch (__device__ globals) ------------------------------
__device__ __align__(16) __half g_WT_hi[(size_t)RR * FOUT * FIN]; // [r][o][k]
__device__ __align__(16) __half g_WT_lo[(size_t)RR * FOUT * FIN];
__device__ __align__(16) __half g_xh[(size_t)NN * FIN];
__device__ int   g_cnt[RR];
__device__ int   g_rcur[RR];
__device__ int   g_estart[RR + 1];
__device__ int   g_tstart[RR + 1];
__device__ int   g_perm[EE];
__device__ int   g_dcnt[NN];
__device__ int   g_dcur[NN];
__device__ int   g_dstart[NN + 1];
__device__ int   g_bsum[20];
__device__ int   g_boff[20];
__device__ int   g_dinv[EE];                     // edge -> dst-sorted rank
__device__ __align__(16) __half g_edge_out[(size_t)EE * FOUT]; // dst-rank order
__device__ float g_res[(size_t)NN * FOUT];
__device__ float g_h[(size_t)NN * FOUT];
__device__ float g_psum[NBN * FOUT];
__device__ float g_psq[NBN * FOUT];
__device__ float g_scale[FOUT];
__device__ float g_shift[FOUT];

// ---------------- helpers ----------------------------------------------------
__device__ __forceinline__ uint32_t smem_u32(const void* p) {
    uint32_t a;
    asm("{ .reg .u64 t; cvta.to.shared.u64 t, %1; cvt.u32.u64 %0, t; }"
        : "=r"(a) : "l"(p));
    return a;
}

__device__ __forceinline__ void ldsm_x4(uint32_t addr, uint32_t& r0, uint32_t& r1,
                                        uint32_t& r2, uint32_t& r3) {
    asm volatile("ldmatrix.sync.aligned.m8n8.x4.shared.b16 {%0,%1,%2,%3}, [%4];"
                 : "=r"(r0), "=r"(r1), "=r"(r2), "=r"(r3) : "r"(addr));
}

__device__ __forceinline__ void mma16816(float* c, const uint32_t* a,
                                         uint32_t b0, uint32_t b1) {
    asm volatile(
        "mma.sync.aligned.m16n8k16.row.col.f32.f16.f16.f32 "
        "{%0,%1,%2,%3}, {%4,%5,%6,%7}, {%8,%9}, {%0,%1,%2,%3};"
        : "+f"(c[0]), "+f"(c[1]), "+f"(c[2]), "+f"(c[3])
        : "r"(a[0]), "r"(a[1]), "r"(a[2]), "r"(a[3]), "r"(b0), "r"(b1));
}

__device__ __forceinline__ void cp16(uint32_t dst, const void* src) {
    asm volatile("cp.async.cg.shared.global [%0], [%1], 16;"
                 :: "r"(dst), "l"(src) : "memory");
}
#define CP_COMMIT() asm volatile("cp.async.commit_group;" ::: "memory")
#define CP_WAIT0()  asm volatile("cp.async.wait_group 0;" ::: "memory")

// ---------------- K1: WT hi/lo fp16, basis read ONCE ---------------------------
// Block = one i (0..127); thread = one o (0..127). Smem: basis slice + comp.
__global__ __launch_bounds__(128) void k_w(const float* __restrict__ basis,
                                           const float* __restrict__ comp) {
    extern __shared__ float swm[];
    float* sb = swm;              // [BB][FIN] = basis[b][i][o] for fixed i
    float* sc = swm + BB * FIN;   // [RR*BB]

    int i = blockIdx.x, o = threadIdx.x;

    for (int b = 0; b < BB; b++)
        sb[b * FIN + o] = basis[(size_t)b * FIN * FOUT + (size_t)i * FOUT + o];
    for (int idx = o; idx < RR * BB; idx += 128)
        sc[idx] = comp[idx];
    __syncthreads();

    float acc[RR];
    #pragma unroll
    for (int r = 0; r < RR; r++) acc[r] = 0.f;

    for (int b = 0; b < BB; b++) {
        float sv = sb[b * FIN + o];
        #pragma unroll
        for (int r = 0; r < RR; r++)
            acc[r] += sc[r * BB + b] * sv;   // sc broadcast across warp
    }

    #pragma unroll 1
    for (int r = 0; r < RR; r++) {
        float a = acc[r];
        __half hi = __float2half(a);
        __half lo = __float2half(a - __half2float(hi));
        size_t tidx = ((size_t)r * FOUT + o) * FIN + i;   // [r][o][k=i]
        g_WT_hi[tidx] = hi;
        g_WT_lo[tidx] = lo;
    }
}

// ---------------- K1b: x -> fp16; also zero counters ---------------------------
__global__ void k_xcvt(const float* __restrict__ x) {
    int i = blockIdx.x * 256 + threadIdx.x;          // half2 index
    if (i < NN * FIN / 2) {
        float2 v = ((const float2*)x)[i];
        ((__half2*)g_xh)[i] = __floats2half2_rn(v.x, v.y);
    }
    if (i < NN) { g_dcnt[i] = 0; g_dcur[i] = 0; }
    if (i < RR) { g_cnt[i] = 0; g_rcur[i] = 0; }
}

// ---------------- K2: histograms ------------------------------------------------
__global__ void k_hist(const int* __restrict__ etype, const int* __restrict__ dst) {
    __shared__ int sh[RR];
    int tid = threadIdx.x;
    if (tid < RR) sh[tid] = 0;
    __syncthreads();
    int e = blockIdx.x * 256 + tid;
    if (e < EE) {
        atomicAdd(&sh[etype[e]], 1);
        atomicAdd(&g_dcnt[dst[e]], 1);
    }
    __syncthreads();
    if (tid < RR && sh[tid]) atomicAdd(&g_cnt[tid], sh[tid]);
}

// ---------------- K3a: local scans (20 blocks x 1000 counts) --------------------
__global__ __launch_bounds__(1024) void k_scan1() {
    __shared__ int sa[1024], sb2[1024];
    int t = threadIdx.x;
    int g = blockIdx.x * 1000;
    int v = (t < 1000) ? g_dcnt[g + t] : 0;
    sa[t] = v;
    __syncthreads();
    int* in = sa; int* out = sb2;
    #pragma unroll
    for (int off = 1; off < 1024; off <<= 1) {
        out[t] = in[t] + ((t >= off) ? in[t - off] : 0);
        __syncthreads();
        int* tmp = in; in = out; out = tmp;
    }
    if (t < 1000) g_dstart[g + t] = in[t] - v;      // local exclusive
    if (t == 999) g_bsum[blockIdx.x] = in[t];       // block total
}

// ---------------- K3b: block offsets + relation scan ------------------------------
__global__ void k_scan2() {
    if (threadIdx.x == 0) {
        int run = 0;
        for (int k = 0; k < 20; k++) { g_boff[k] = run; run += g_bsum[k]; }
        g_dstart[NN] = run;
        int es = 0, ts = 0;
        for (int r = 0; r < RR; r++) {
            g_estart[r] = es; g_tstart[r] = ts;
            es += g_cnt[r];
            ts += (g_cnt[r] + TILE_M - 1) / TILE_M;
        }
        g_estart[RR] = es; g_tstart[RR] = ts;
    }
}

// ---------------- K3c: add block offsets -------------------------------------------
__global__ __launch_bounds__(1024) void k_scan3() {
    int t = threadIdx.x;
    if (t < 1000) g_dstart[blockIdx.x * 1000 + t] += g_boff[blockIdx.x];
}

// ---------------- K4: scatter ------------------------------------------------------
__global__ void k_scatter(const int* __restrict__ etype, const int* __restrict__ dst) {
    __shared__ int s_cnt[RR], s_base[RR];
    int tid = threadIdx.x;
    if (tid < RR) s_cnt[tid] = 0;
    __syncthreads();
    int e = blockIdx.x * 256 + tid;
    bool valid = (e < EE);
    int r = 0, lrank = 0;
    if (valid) { r = etype[e]; lrank = atomicAdd(&s_cnt[r], 1); }
    __syncthreads();
    if (tid < RR && s_cnt[tid] > 0) s_base[tid] = atomicAdd(&g_rcur[tid], s_cnt[tid]);
    __syncthreads();
    if (valid) {
        g_perm[g_estart[r] + s_base[r] + lrank] = e;
        int d = dst[e];
        g_dinv[e] = g_dstart[d] + atomicAdd(&g_dcur[d], 1);
    }
}

// merged k-step: A loaded once, both B products accumulate into acc
#define KSTEP(S, aA) do { \
    uint32_t ka = (aA) + (S) * 32; \
    uint32_t a0[4], a1[4]; \
    ldsm_x4(ka,             a0[0], a0[1], a0[2], a0[3]); \
    ldsm_x4(ka + 16 * ROWB, a1[0], a1[1], a1[2], a1[3]); \
    uint32_t kbh = bAddrHi + (S) * 32, kbl = bAddrLo + (S) * 32; \
    _Pragma("unroll") \
    for (int pr = 0; pr < 4; pr++) { \
        uint32_t b0, b1, b2, b3; \
        ldsm_x4(kbh + pr * 16 * ROWB, b0, b1, b2, b3); \
        int nt = pr * 2; \
        mma16816(acc[0][nt],     a0, b0, b1); \
        mma16816(acc[1][nt],     a1, b0, b1); \
        mma16816(acc[0][nt + 1], a0, b2, b3); \
        mma16816(acc[1][nt + 1], a1, b2, b3); \
    } \
    _Pragma("unroll") \
    for (int pr = 0; pr < 4; pr++) { \
        uint32_t b0, b1, b2, b3; \
        ldsm_x4(kbl + pr * 16 * ROWB, b0, b1, b2, b3); \
        int nt = pr * 2; \
        mma16816(acc[0][nt],     a0, b0, b1); \
        mma16816(acc[1][nt],     a1, b0, b1); \
        mma16816(acc[0][nt + 1], a0, b2, b3); \
        mma16816(acc[1][nt + 1], a1, b2, b3); \
    } \
} while (0)

// ---------------- K5: persistent HMMA GEMM: A=fp16(x), B=W hi+lo ----------------
__global__ __launch_bounds__(256) void k_gemm(const int* __restrict__ src,
                                              const float* __restrict__ norm) {
    extern __shared__ char dsm[];
    __shared__ int   s_src[2][TILE_M];
    __shared__ float s_nrm[2][TILE_M];
    __shared__ int   s_dinv[2][TILE_M];

    char* Abuf[2] = { dsm, dsm + ATILE };
    char* B_hi = dsm + 2 * ATILE;
    char* B_lo = dsm + 3 * ATILE;

    int tid = threadIdx.x;
    int T = g_tstart[RR];
    int per = (T + GEMM_GRID - 1) / GEMM_GRID;
    int t0 = blockIdx.x * per;
    int t1 = t0 + per; if (t1 > T) t1 = T;
    if (t0 >= t1) return;

    int lane = tid & 31, w = tid >> 5;
    int wm = w & 3, wn = w >> 2;
    int rm = wm * 32;
    uint32_t aLane = (uint32_t)((rm + (lane & 15)) * ROWB + ((lane >> 4) << 4));
    uint32_t bLane = (uint32_t)((wn * 64 + ((lane >> 4) << 3) + (lane & 7)) * ROWB
                                + (((lane >> 3) & 1) << 4));
    uint32_t aBase[2] = { smem_u32(Abuf[0]) + aLane, smem_u32(Abuf[1]) + aLane };
    uint32_t bAddrHi = smem_u32(B_hi) + bLane;
    uint32_t bAddrLo = smem_u32(B_lo) + bLane;

    int r = 0;
    while (g_tstart[r + 1] <= t0) r++;

    // ---- sync meta for tile t0 (buf 0) ----
    {
        int ebase = g_estart[r] + (t0 - g_tstart[r]) * TILE_M;
        int cnt = g_estart[r + 1] - ebase; if (cnt > TILE_M) cnt = TILE_M;
        if (tid < TILE_M) {
            int sv = 0, dv = -1; float nm = 0.f;
            if (tid < cnt) {
                int e = g_perm[ebase + tid];
                sv = src[e]; nm = norm[e]; dv = g_dinv[e];
            }
            s_src[0][tid] = sv; s_nrm[0][tid] = nm; s_dinv[0][tid] = dv;
        }
    }
    __syncthreads();

    // ---- B (hi+lo) fill for r, A fill for t0 ----
    {
        const char* WH = (const char*)g_WT_hi + (size_t)r * 32768;
        const char* WL = (const char*)g_WT_lo + (size_t)r * 32768;
        #pragma unroll
        for (int it = 0; it < 16; it++) {
            int id = tid + it * 256;
            int arr = id >> 11, o = (id >> 4) & 127, j = id & 15;
            cp16(smem_u32((arr ? B_lo : B_hi) + o * ROWB + j * 16),
                 (arr ? WL : WH) + o * 256 + j * 16);
        }
        #pragma unroll
        for (int it = 0; it < 8; it++) {
            int id = tid + it * 256;
            int m = id >> 4, j = id & 15;
            cp16(smem_u32(Abuf[0] + m * ROWB + j * 16),
                 (const char*)g_xh + (size_t)s_src[0][m] * 256 + j * 16);
        }
        CP_COMMIT();
    }
    CP_WAIT0();
    __syncthreads();

    int buf = 0;
    for (int t = t0; t < t1; t++) {
        bool hasNext = (t + 1 < t1);
        int rn = r;
        if (hasNext) { while (g_tstart[rn + 1] <= t + 1) rn++; }

        // 1. meta prefetch for next tile (registers; latency hidden by steps 0-3)
        int m_src = 0, m_dinv = -1; float m_nrm = 0.f;
        if (hasNext && tid < TILE_M) {
            int ebase = g_estart[rn] + (t + 1 - g_tstart[rn]) * TILE_M;
            int cnt = g_estart[rn + 1] - ebase; if (cnt > TILE_M) cnt = TILE_M;
            if (tid < cnt) {
                int e = g_perm[ebase + tid];
                m_src = src[e]; m_nrm = norm[e]; m_dinv = g_dinv[e];
            }
        }

        float acc[2][8][4];
        #pragma unroll
        for (int a = 0; a < 2; a++)
            #pragma unroll
            for (int b = 0; b < 8; b++)
                #pragma unroll
                for (int c = 0; c < 4; c++) acc[a][b][c] = 0.f;

        uint32_t aA = aBase[buf];

        // 2. mainloop first half (k-steps 0-3)
        #pragma unroll
        for (int s = 0; s < 4; s++) KSTEP(s, aA);

        // 3. publish next meta + issue A prefetch
        if (hasNext && tid < TILE_M) {
            s_src[buf ^ 1][tid] = m_src;
            s_nrm[buf ^ 1][tid] = m_nrm;
            s_dinv[buf ^ 1][tid] = m_dinv;
        }
        __syncthreads();
        if (hasNext) {
            int nb = buf ^ 1;
            #pragma unroll
            for (int it = 0; it < 8; it++) {
                int id = tid + it * 256;
                int m = id >> 4, j = id & 15;
                cp16(smem_u32(Abuf[nb] + m * ROWB + j * 16),
                     (const char*)g_xh + (size_t)s_src[nb][m] * 256 + j * 16);
            }
            CP_COMMIT();
        }

        // 4. mainloop second half (k-steps 4-7)
        #pragma unroll
        for (int s = 4; s < 8; s++) KSTEP(s, aA);

        // 5. epilogue: scale by norm, store fp16 rows at dst-rank
        {
            int colBase = wn * 64 + (lane & 3) * 2;
            #pragma unroll
            for (int mt = 0; mt < 2; mt++) {
                int row0 = rm + mt * 16 + (lane >> 2);
                int d0 = s_dinv[buf][row0], d1 = s_dinv[buf][row0 + 8];
                float n0 = s_nrm[buf][row0], n1 = s_nrm[buf][row0 + 8];
                __half* p0 = (d0 >= 0) ? g_edge_out + (size_t)d0 * FOUT + colBase : (__half*)0;
                __half* p1 = (d1 >= 0) ? g_edge_out + (size_t)d1 * FOUT + colBase : (__half*)0;
                #pragma unroll
                for (int nt = 0; nt < 8; nt++) {
                    if (p0) *(__half2*)(p0 + nt * 8) =
                        __floats2half2_rn(acc[mt][nt][0] * n0, acc[mt][nt][1] * n0);
                    if (p1) *(__half2*)(p1 + nt * 8) =
                        __floats2half2_rn(acc[mt][nt][2] * n1, acc[mt][nt][3] * n1);
                }
            }
        }

        // 6. B reload on relation change, then wait for A prefetch
        if (hasNext) {
            if (rn != r) {
                __syncthreads();   // all warps done reading B
                const char* WH = (const char*)g_WT_hi + (size_t)rn * 32768;
                const char* WL = (const char*)g_WT_lo + (size_t)rn * 32768;
                #pragma unroll
                for (int it = 0; it < 16; it++) {
                    int id = tid + it * 256;
                    int arr = id >> 11, o = (id >> 4) & 127, j = id & 15;
                    cp16(smem_u32((arr ? B_lo : B_hi) + o * ROWB + j * 16),
                         (arr ? WL : WH) + o * 256 + j * 16);
                }
                CP_COMMIT();
                r = rn;
            }
            CP_WAIT0();
            __syncthreads();
        }
        buf ^= 1;
    }
}

// ---------------- K5b: residual GEMM g_res = relu(x @ W_res + b_res) ------------
__global__ __launch_bounds__(256) void k_res(const float* __restrict__ x,
                                             const float* __restrict__ Wres,
                                             const float* __restrict__ bres) {
    __shared__ float sAT[128][36];
    int tid = threadIdx.x;
    int n0 = blockIdx.x * 32;

    for (int idx = tid; idx < 32 * 32; idx += 256) {
        int i = idx & 31, j = idx >> 5;
        float4 v = __ldg((const float4*)(x + (size_t)(n0 + i) * FIN) + j);
        int k = j << 2;
        sAT[k + 0][i] = v.x; sAT[k + 1][i] = v.y;
        sAT[k + 2][i] = v.z; sAT[k + 3][i] = v.w;
    }
    __syncthreads();

    int tx = tid & 31, ty = tid >> 5;
    const float4* W4 = (const float4*)Wres;
    float c00=0,c01=0,c02=0,c03=0, c10=0,c11=0,c12=0,c13=0;
    float c20=0,c21=0,c22=0,c23=0, c30=0,c31=0,c32=0,c33=0;

    #pragma unroll 4
    for (int k = 0; k < 128; k++) {
        float4 b = __ldg(&W4[(k << 5) + tx]);
        float4 a = *(const float4*)&sAT[k][ty << 2];
        c00 += a.x*b.x; c01 += a.x*b.y; c02 += a.x*b.z; c03 += a.x*b.w;
        c10 += a.y*b.x; c11 += a.y*b.y; c12 += a.y*b.z; c13 += a.y*b.w;
        c20 += a.z*b.x; c21 += a.z*b.y; c22 += a.z*b.z; c23 += a.z*b.w;
        c30 += a.w*b.x; c31 += a.w*b.y; c32 += a.w*b.z; c33 += a.w*b.w;
    }

    float4 br = __ldg(&((const float4*)bres)[tx]);
    float4 rows[4] = {
        make_float4(fmaxf(c00+br.x,0.f), fmaxf(c01+br.y,0.f), fmaxf(c02+br.z,0.f), fmaxf(c03+br.w,0.f)),
        make_float4(fmaxf(c10+br.x,0.f), fmaxf(c11+br.y,0.f), fmaxf(c12+br.z,0.f), fmaxf(c13+br.w,0.f)),
        make_float4(fmaxf(c20+br.x,0.f), fmaxf(c21+br.y,0.f), fmaxf(c22+br.z,0.f), fmaxf(c23+br.w,0.f)),
        make_float4(fmaxf(c30+br.x,0.f), fmaxf(c31+br.y,0.f), fmaxf(c32+br.z,0.f), fmaxf(c33+br.w,0.f))
    };
    #pragma unroll
    for (int i = 0; i < 4; i++)
        *(float4*)(g_res + (size_t)(n0 + (ty << 2) + i) * FOUT + (tx << 2)) = rows[i];
}

// ---------------- K6: segmented reduce (half2 stream) + relu + residual ----------
__global__ __launch_bounds__(128) void k_reduce(const float* __restrict__ h_bias) {
    int n = blockIdx.x * 2 + (threadIdx.x >> 6);
    int c = threadIdx.x & 63;
    int s = g_dstart[n], e = g_dstart[n + 1];
    float2 acc = make_float2(0.f, 0.f);
    const __half2* p = (const __half2*)g_edge_out + (size_t)s * 64 + c;
    for (int j = s; j < e; j++, p += 64) {
        float2 f = __half22float2(*p);
        acc.x += f.x; acc.y += f.y;
    }
    float2 bv = __ldg(&((const float2*)h_bias)[c]);
    acc.x = fmaxf(acc.x + bv.x, 0.f);
    acc.y = fmaxf(acc.y + bv.y, 0.f);
    float2 rv = ((const float2*)g_res)[(size_t)n * 64 + c];
    acc.x += rv.x; acc.y += rv.y;
    ((float2*)g_h)[(size_t)n * 64 + c] = acc;
}

// ---------------- K7/K8/K9: BN -----------------------------------------------------
__global__ __launch_bounds__(128) void k_bnsum() {
    int b = blockIdx.x, o = threadIdx.x;
    float s = 0.f, sq = 0.f;
    int r0 = b * (NN / NBN), r1 = r0 + (NN / NBN);
    for (int n = r0; n < r1; n++) {
        float v = g_h[(size_t)n * FOUT + o];
        s += v; sq += v * v;
    }
    g_psum[b * FOUT + o] = s;
    g_psq[b * FOUT + o] = sq;
}

__global__ __launch_bounds__(128) void k_bnfin(const float* __restrict__ gamma,
                                               const float* __restrict__ beta) {
    int o = threadIdx.x;
    float s = 0.f, sq = 0.f;
    for (int b = 0; b < NBN; b++) { s += g_psum[b * FOUT + o]; sq += g_psq[b * FOUT + o]; }
    float mean = s / (float)NN;
    float var = sq / (float)NN - mean * mean;
    float sc = gamma[o] * rsqrtf(var + 1e-5f);
    g_scale[o] = sc;
    g_shift[o] = beta[o] - mean * sc;
}

__global__ void k_out(float* __restrict__ out) {
    int i = blockIdx.x * 256 + threadIdx.x;
    if (i < NN * FOUT) {
        int o = i & 127;
        out[i] = g_h[i] * g_scale[o] + g_shift[o];
    }
}

// ---------------- launch -------------------------------------------------------------
extern "C" void kernel_launch(void* const* d_in, const int* in_sizes, int n_in,
                              void* d_out, int out_size) {
    const float* node_feats = (const float*)d_in[0];
    const int*   src        = (const int*)d_in[1];
    const int*   dst        = (const int*)d_in[2];
    const int*   etype      = (const int*)d_in[3];
    const float* norm       = (const float*)d_in[4];
    const float* basis      = (const float*)d_in[5];
    const float* comp       = (const float*)d_in[6];
    const float* h_bias     = (const float*)d_in[7];
    const float* W_res      = (const float*)d_in[8];
    const float* b_res      = (const float*)d_in[9];
    const float* gamma      = (const float*)d_in[10];
    const float* beta       = (const float*)d_in[11];
    float* out = (float*)d_out;

    const int DSMEM   = 4 * ATILE;                      // 139264 B
    const int KW_SMEM = (BB * FIN + RR * BB) * 4;       // 50180 B
    cudaFuncSetAttribute(k_gemm, cudaFuncAttributeMaxDynamicSharedMemorySize, DSMEM);
    cudaFuncSetAttribute(k_w, cudaFuncAttributeMaxDynamicSharedMemorySize, KW_SMEM);

    k_w<<<FIN, 128, KW_SMEM>>>(basis, comp);
    k_xcvt<<<(NN * FIN / 2 + 255) / 256, 256>>>(node_feats);
    k_hist<<<(EE + 255) / 256, 256>>>(etype, dst);
    k_scan1<<<20, 1024>>>();
    k_scan2<<<1, 32>>>();
    k_scan3<<<20, 1024>>>();
    k_scatter<<<(EE + 255) / 256, 256>>>(etype, dst);
    k_gemm<<<GEMM_GRID, 256, DSMEM>>>(src, norm);
    k_res<<<NN / 32, 256>>>(node_feats, W_res, b_res);
    k_reduce<<<NN / 2, 128>>>(h_bias);
    k_bnsum<<<NBN, 128>>>();
    k_bnfin<<<1, 128>>>(gamma, beta);
    k_out<<<(NN * FOUT + 255) / 256, 256>>>(out);
    (void)in_sizes; (void)n_in; (void)out_size;
}

// round 7
// speedup vs baseline: 3.6261x; 1.0403x over previous
#include <cuda_runtime.h>
#include <cuda_fp16.h>
#include <stdint.h>

// Problem constants
#define NN   20000
#define EE   640000
#define FIN  128
#define FOUT 128
#define RR   65
#define BB   65
#define TILE_M 128
#define NBN  100

#define ROWB 272                  // bytes per smem tile row (136 halves, padded)
#define ATILE (128 * ROWB)        // 34816 B
#define GEMM_GRID 296             // 2 CTAs per SM

// ---------------- scratch (__device__ globals) ------------------------------
__device__ __align__(16) __half g_WT_hi[(size_t)RR * FOUT * FIN]; // [r][o][k]
__device__ __align__(16) __half g_WT_lo[(size_t)RR * FOUT * FIN];
__device__ __align__(16) __half g_xh[(size_t)NN * FIN];
__device__ int   g_cnt[RR];
__device__ int   g_rcur[RR];
__device__ int   g_estart[RR + 1];
__device__ int   g_tstart[RR + 1];
__device__ int   g_perm[EE];
__device__ int   g_dcnt[NN];
__device__ int   g_dcur[NN];
__device__ int   g_dstart[NN + 1];
__device__ int   g_bsum[20];
__device__ int   g_boff[20];
__device__ int   g_dinv[EE];                     // edge -> dst-sorted rank
__device__ __align__(16) __half g_edge_out[(size_t)EE * FOUT]; // dst-rank order
__device__ float g_res[(size_t)NN * FOUT];
__device__ float g_h[(size_t)NN * FOUT];
__device__ float g_psum[NBN * FOUT];
__device__ float g_psq[NBN * FOUT];
__device__ float g_scale[FOUT];
__device__ float g_shift[FOUT];

// ---------------- helpers ----------------------------------------------------
__device__ __forceinline__ uint32_t smem_u32(const void* p) {
    uint32_t a;
    asm("{ .reg .u64 t; cvta.to.shared.u64 t, %1; cvt.u32.u64 %0, t; }"
        : "=r"(a) : "l"(p));
    return a;
}

__device__ __forceinline__ void ldsm_x4(uint32_t addr, uint32_t& r0, uint32_t& r1,
                                        uint32_t& r2, uint32_t& r3) {
    asm volatile("ldmatrix.sync.aligned.m8n8.x4.shared.b16 {%0,%1,%2,%3}, [%4];"
                 : "=r"(r0), "=r"(r1), "=r"(r2), "=r"(r3) : "r"(addr));
}

__device__ __forceinline__ void mma16816(float* c, const uint32_t* a,
                                         uint32_t b0, uint32_t b1) {
    asm volatile(
        "mma.sync.aligned.m16n8k16.row.col.f32.f16.f16.f32 "
        "{%0,%1,%2,%3}, {%4,%5,%6,%7}, {%8,%9}, {%0,%1,%2,%3};"
        : "+f"(c[0]), "+f"(c[1]), "+f"(c[2]), "+f"(c[3])
        : "r"(a[0]), "r"(a[1]), "r"(a[2]), "r"(a[3]), "r"(b0), "r"(b1));
}

__device__ __forceinline__ void cp16(uint32_t dst, const void* src) {
    asm volatile("cp.async.cg.shared.global [%0], [%1], 16;"
                 :: "r"(dst), "l"(src) : "memory");
}
#define CP_COMMIT() asm volatile("cp.async.commit_group;" ::: "memory")
#define CP_WAIT0()  asm volatile("cp.async.wait_group 0;" ::: "memory")

// ---------------- K1: WT hi/lo fp16, basis read once ---------------------------
__global__ __launch_bounds__(128) void k_w(const float* __restrict__ basis,
                                           const float* __restrict__ comp) {
    extern __shared__ float swm[];
    float* sb = swm;              // [BB][FIN] = basis[b][i][o] for fixed i
    float* sc = swm + BB * FIN;   // [RR*BB]

    int i = blockIdx.x, o = threadIdx.x;

    for (int b = 0; b < BB; b++)
        sb[b * FIN + o] = basis[(size_t)b * FIN * FOUT + (size_t)i * FOUT + o];
    for (int idx = o; idx < RR * BB; idx += 128)
        sc[idx] = comp[idx];
    __syncthreads();

    float acc[RR];
    #pragma unroll
    for (int r = 0; r < RR; r++) acc[r] = 0.f;

    for (int b = 0; b < BB; b++) {
        float sv = sb[b * FIN + o];
        #pragma unroll
        for (int r = 0; r < RR; r++)
            acc[r] += sc[r * BB + b] * sv;
    }

    #pragma unroll 1
    for (int r = 0; r < RR; r++) {
        float a = acc[r];
        __half hi = __float2half(a);
        __half lo = __float2half(a - __half2float(hi));
        size_t tidx = ((size_t)r * FOUT + o) * FIN + i;   // [r][o][k=i]
        g_WT_hi[tidx] = hi;
        g_WT_lo[tidx] = lo;
    }
}

// ---------------- K1b: x -> fp16; also zero counters ---------------------------
__global__ void k_xcvt(const float* __restrict__ x) {
    int i = blockIdx.x * 256 + threadIdx.x;          // half2 index
    if (i < NN * FIN / 2) {
        float2 v = ((const float2*)x)[i];
        ((__half2*)g_xh)[i] = __floats2half2_rn(v.x, v.y);
    }
    if (i < NN) { g_dcnt[i] = 0; g_dcur[i] = 0; }
    if (i < RR) { g_cnt[i] = 0; g_rcur[i] = 0; }
}

// ---------------- K2: histograms ------------------------------------------------
__global__ void k_hist(const int* __restrict__ etype, const int* __restrict__ dst) {
    __shared__ int sh[RR];
    int tid = threadIdx.x;
    if (tid < RR) sh[tid] = 0;
    __syncthreads();
    int e = blockIdx.x * 256 + tid;
    if (e < EE) {
        atomicAdd(&sh[etype[e]], 1);
        atomicAdd(&g_dcnt[dst[e]], 1);
    }
    __syncthreads();
    if (tid < RR && sh[tid]) atomicAdd(&g_cnt[tid], sh[tid]);
}

// ---------------- K3a: local scans (20 blocks x 1000 counts) --------------------
__global__ __launch_bounds__(1024) void k_scan1() {
    __shared__ int sa[1024], sb2[1024];
    int t = threadIdx.x;
    int g = blockIdx.x * 1000;
    int v = (t < 1000) ? g_dcnt[g + t] : 0;
    sa[t] = v;
    __syncthreads();
    int* in = sa; int* out = sb2;
    #pragma unroll
    for (int off = 1; off < 1024; off <<= 1) {
        out[t] = in[t] + ((t >= off) ? in[t - off] : 0);
        __syncthreads();
        int* tmp = in; in = out; out = tmp;
    }
    if (t < 1000) g_dstart[g + t] = in[t] - v;      // local exclusive
    if (t == 999) g_bsum[blockIdx.x] = in[t];       // block total
}

// ---------------- K3b: block offsets + relation scan ------------------------------
__global__ void k_scan2() {
    if (threadIdx.x == 0) {
        int run = 0;
        for (int k = 0; k < 20; k++) { g_boff[k] = run; run += g_bsum[k]; }
        g_dstart[NN] = run;
        int es = 0, ts = 0;
        for (int r = 0; r < RR; r++) {
            g_estart[r] = es; g_tstart[r] = ts;
            es += g_cnt[r];
            ts += (g_cnt[r] + TILE_M - 1) / TILE_M;
        }
        g_estart[RR] = es; g_tstart[RR] = ts;
    }
}

// ---------------- K3c: add block offsets -------------------------------------------
__global__ __launch_bounds__(1024) void k_scan3() {
    int t = threadIdx.x;
    if (t < 1000) g_dstart[blockIdx.x * 1000 + t] += g_boff[blockIdx.x];
}

// ---------------- K4: scatter ------------------------------------------------------
__global__ void k_scatter(const int* __restrict__ etype, const int* __restrict__ dst) {
    __shared__ int s_cnt[RR], s_base[RR];
    int tid = threadIdx.x;
    if (tid < RR) s_cnt[tid] = 0;
    __syncthreads();
    int e = blockIdx.x * 256 + tid;
    bool valid = (e < EE);
    int r = 0, lrank = 0;
    if (valid) { r = etype[e]; lrank = atomicAdd(&s_cnt[r], 1); }
    __syncthreads();
    if (tid < RR && s_cnt[tid] > 0) s_base[tid] = atomicAdd(&g_rcur[tid], s_cnt[tid]);
    __syncthreads();
    if (valid) {
        g_perm[g_estart[r] + s_base[r] + lrank] = e;
        int d = dst[e];
        g_dinv[e] = g_dstart[d] + atomicAdd(&g_dcur[d], 1);
    }
}

// merged k-step: A loaded once, both B products accumulate into acc
#define KSTEP(S, aA) do { \
    uint32_t ka = (aA) + (S) * 32; \
    uint32_t a0[4], a1[4]; \
    ldsm_x4(ka,             a0[0], a0[1], a0[2], a0[3]); \
    ldsm_x4(ka + 16 * ROWB, a1[0], a1[1], a1[2], a1[3]); \
    uint32_t kbh = bAddrHi + (S) * 32, kbl = bAddrLo + (S) * 32; \
    _Pragma("unroll") \
    for (int pr = 0; pr < 4; pr++) { \
        uint32_t b0, b1, b2, b3; \
        ldsm_x4(kbh + pr * 16 * ROWB, b0, b1, b2, b3); \
        int nt = pr * 2; \
        mma16816(acc[0][nt],     a0, b0, b1); \
        mma16816(acc[1][nt],     a1, b0, b1); \
        mma16816(acc[0][nt + 1], a0, b2, b3); \
        mma16816(acc[1][nt + 1], a1, b2, b3); \
    } \
    _Pragma("unroll") \
    for (int pr = 0; pr < 4; pr++) { \
        uint32_t b0, b1, b2, b3; \
        ldsm_x4(kbl + pr * 16 * ROWB, b0, b1, b2, b3); \
        int nt = pr * 2; \
        mma16816(acc[0][nt],     a0, b0, b1); \
        mma16816(acc[1][nt],     a1, b0, b1); \
        mma16816(acc[0][nt + 1], a0, b2, b3); \
        mma16816(acc[1][nt + 1], a1, b2, b3); \
    } \
} while (0)

// ---------------- K5: persistent HMMA GEMM, 2 CTAs/SM ---------------------------
// smem: single A tile + B_hi + B_lo = 104448 B dynamic -> 2 CTAs per SM.
// Cross-CTA overlap hides A-fill, meta LDG, epilogue drain, B reloads.
__global__ __launch_bounds__(256, 2) void k_gemm(const int* __restrict__ src,
                                                 const float* __restrict__ norm) {
    extern __shared__ char dsm[];
    __shared__ int   s_src[TILE_M];
    __shared__ float s_nrm[TILE_M];
    __shared__ int   s_dinv[TILE_M];

    char* A    = dsm;
    char* B_hi = dsm + ATILE;
    char* B_lo = dsm + 2 * ATILE;

    int tid = threadIdx.x;
    int T = g_tstart[RR];
    int per = (T + GEMM_GRID - 1) / GEMM_GRID;
    int t0 = blockIdx.x * per;
    int t1 = t0 + per; if (t1 > T) t1 = T;
    if (t0 >= t1) return;

    int lane = tid & 31, w = tid >> 5;
    int wm = w & 3, wn = w >> 2;
    int rm = wm * 32;
    uint32_t aLane = (uint32_t)((rm + (lane & 15)) * ROWB + ((lane >> 4) << 4));
    uint32_t bLane = (uint32_t)((wn * 64 + ((lane >> 4) << 3) + (lane & 7)) * ROWB
                                + (((lane >> 3) & 1) << 4));
    uint32_t aBase   = smem_u32(A) + aLane;
    uint32_t bAddrHi = smem_u32(B_hi) + bLane;
    uint32_t bAddrLo = smem_u32(B_lo) + bLane;

    int r = 0;
    while (g_tstart[r + 1] <= t0) r++;

    // ---- B (hi+lo) fill for first relation ----
    {
        const char* WH = (const char*)g_WT_hi + (size_t)r * 32768;
        const char* WL = (const char*)g_WT_lo + (size_t)r * 32768;
        #pragma unroll
        for (int it = 0; it < 16; it++) {
            int id = tid + it * 256;
            int arr = id >> 11, o = (id >> 4) & 127, j = id & 15;
            cp16(smem_u32((arr ? B_lo : B_hi) + o * ROWB + j * 16),
                 (arr ? WL : WH) + o * 256 + j * 16);
        }
        CP_COMMIT();
    }

    // ---- meta for tile t0 (sync) ----
    if (tid < TILE_M) {
        int ebase = g_estart[r] + (t0 - g_tstart[r]) * TILE_M;
        int cnt = g_estart[r + 1] - ebase; if (cnt > TILE_M) cnt = TILE_M;
        int sv = 0, dv = -1; float nm = 0.f;
        if (tid < cnt) {
            int e = g_perm[ebase + tid];
            sv = src[e]; nm = norm[e]; dv = g_dinv[e];
        }
        s_src[tid] = sv; s_nrm[tid] = nm; s_dinv[tid] = dv;
    }
    __syncthreads();

    for (int t = t0; t < t1; t++) {
        bool hasNext = (t + 1 < t1);
        int rn = r;
        if (hasNext) { while (g_tstart[rn + 1] <= t + 1) rn++; }

        // 1. meta prefetch for next tile into registers (LDG latency hidden
        //    by A-fill wait + mainloop)
        int m_src = 0, m_dinv = -1; float m_nrm = 0.f;
        if (hasNext && tid < TILE_M) {
            int ebase = g_estart[rn] + (t + 1 - g_tstart[rn]) * TILE_M;
            int cnt = g_estart[rn + 1] - ebase; if (cnt > TILE_M) cnt = TILE_M;
            if (tid < cnt) {
                int e = g_perm[ebase + tid];
                m_src = src[e]; m_nrm = norm[e]; m_dinv = g_dinv[e];
            }
        }

        // 2. A fill for this tile (cp.async from L2-resident g_xh)
        #pragma unroll
        for (int it = 0; it < 8; it++) {
            int id = tid + it * 256;
            int m = id >> 4, j = id & 15;
            cp16(smem_u32(A + m * ROWB + j * 16),
                 (const char*)g_xh + (size_t)s_src[m] * 256 + j * 16);
        }
        CP_COMMIT();
        CP_WAIT0();                // also drains any pending B fill
        __syncthreads();

        // 3. mainloop
        float acc[2][8][4];
        #pragma unroll
        for (int a = 0; a < 2; a++)
            #pragma unroll
            for (int b = 0; b < 8; b++)
                #pragma unroll
                for (int c = 0; c < 4; c++) acc[a][b][c] = 0.f;

        #pragma unroll
        for (int s = 0; s < 8; s++) KSTEP(s, aBase);

        // 4. epilogue: scale by norm, store fp16 rows at dst-rank
        {
            int colBase = wn * 64 + (lane & 3) * 2;
            #pragma unroll
            for (int mt = 0; mt < 2; mt++) {
                int row0 = rm + mt * 16 + (lane >> 2);
                int d0 = s_dinv[row0], d1 = s_dinv[row0 + 8];
                float n0 = s_nrm[row0], n1 = s_nrm[row0 + 8];
                __half* p0 = (d0 >= 0) ? g_edge_out + (size_t)d0 * FOUT + colBase : (__half*)0;
                __half* p1 = (d1 >= 0) ? g_edge_out + (size_t)d1 * FOUT + colBase : (__half*)0;
                #pragma unroll
                for (int nt = 0; nt < 8; nt++) {
                    if (p0) *(__half2*)(p0 + nt * 8) =
                        __floats2half2_rn(acc[mt][nt][0] * n0, acc[mt][nt][1] * n0);
                    if (p1) *(__half2*)(p1 + nt * 8) =
                        __floats2half2_rn(acc[mt][nt][2] * n1, acc[mt][nt][3] * n1);
                }
            }
        }

        // 5. publish next meta; B reload on relation change
        __syncthreads();           // all reads of A, B, meta done
        if (hasNext) {
            if (tid < TILE_M) {
                s_src[tid] = m_src; s_nrm[tid] = m_nrm; s_dinv[tid] = m_dinv;
            }
            if (rn != r) {
                const char* WH = (const char*)g_WT_hi + (size_t)rn * 32768;
                const char* WL = (const char*)g_WT_lo + (size_t)rn * 32768;
                #pragma unroll
                for (int it = 0; it < 16; it++) {
                    int id = tid + it * 256;
                    int arr = id >> 11, o = (id >> 4) & 127, j = id & 15;
                    cp16(smem_u32((arr ? B_lo : B_hi) + o * ROWB + j * 16),
                         (arr ? WL : WH) + o * 256 + j * 16);
                }
                CP_COMMIT();
                r = rn;
            }
            __syncthreads();       // meta visible before next A fill reads it
        }
    }
}

// ---------------- K5b: residual GEMM g_res = relu(x @ W_res + b_res) ------------
__global__ __launch_bounds__(256) void k_res(const float* __restrict__ x,
                                             const float* __restrict__ Wres,
                                             const float* __restrict__ bres) {
    __shared__ float sAT[128][36];
    int tid = threadIdx.x;
    int n0 = blockIdx.x * 32;

    for (int idx = tid; idx < 32 * 32; idx += 256) {
        int i = idx & 31, j = idx >> 5;
        float4 v = __ldg((const float4*)(x + (size_t)(n0 + i) * FIN) + j);
        int k = j << 2;
        sAT[k + 0][i] = v.x; sAT[k + 1][i] = v.y;
        sAT[k + 2][i] = v.z; sAT[k + 3][i] = v.w;
    }
    __syncthreads();

    int tx = tid & 31, ty = tid >> 5;
    const float4* W4 = (const float4*)Wres;
    float c00=0,c01=0,c02=0,c03=0, c10=0,c11=0,c12=0,c13=0;
    float c20=0,c21=0,c22=0,c23=0, c30=0,c31=0,c32=0,c33=0;

    #pragma unroll 4
    for (int k = 0; k < 128; k++) {
        float4 b = __ldg(&W4[(k << 5) + tx]);
        float4 a = *(const float4*)&sAT[k][ty << 2];
        c00 += a.x*b.x; c01 += a.x*b.y; c02 += a.x*b.z; c03 += a.x*b.w;
        c10 += a.y*b.x; c11 += a.y*b.y; c12 += a.y*b.z; c13 += a.y*b.w;
        c20 += a.z*b.x; c21 += a.z*b.y; c22 += a.z*b.z; c23 += a.z*b.w;
        c30 += a.w*b.x; c31 += a.w*b.y; c32 += a.w*b.z; c33 += a.w*b.w;
    }

    float4 br = __ldg(&((const float4*)bres)[tx]);
    float4 rows[4] = {
        make_float4(fmaxf(c00+br.x,0.f), fmaxf(c01+br.y,0.f), fmaxf(c02+br.z,0.f), fmaxf(c03+br.w,0.f)),
        make_float4(fmaxf(c10+br.x,0.f), fmaxf(c11+br.y,0.f), fmaxf(c12+br.z,0.f), fmaxf(c13+br.w,0.f)),
        make_float4(fmaxf(c20+br.x,0.f), fmaxf(c21+br.y,0.f), fmaxf(c22+br.z,0.f), fmaxf(c23+br.w,0.f)),
        make_float4(fmaxf(c30+br.x,0.f), fmaxf(c31+br.y,0.f), fmaxf(c32+br.z,0.f), fmaxf(c33+br.w,0.f))
    };
    #pragma unroll
    for (int i = 0; i < 4; i++)
        *(float4*)(g_res + (size_t)(n0 + (ty << 2) + i) * FOUT + (tx << 2)) = rows[i];
}

// ---------------- K6: segmented reduce (half2 stream) + relu + residual ----------
__global__ __launch_bounds__(128) void k_reduce(const float* __restrict__ h_bias) {
    int n = blockIdx.x * 2 + (threadIdx.x >> 6);
    int c = threadIdx.x & 63;
    int s = g_dstart[n], e = g_dstart[n + 1];
    float2 acc = make_float2(0.f, 0.f);
    const __half2* p = (const __half2*)g_edge_out + (size_t)s * 64 + c;
    for (int j = s; j < e; j++, p += 64) {
        float2 f = __half22float2(*p);
        acc.x += f.x; acc.y += f.y;
    }
    float2 bv = __ldg(&((const float2*)h_bias)[c]);
    acc.x = fmaxf(acc.x + bv.x, 0.f);
    acc.y = fmaxf(acc.y + bv.y, 0.f);
    float2 rv = ((const float2*)g_res)[(size_t)n * 64 + c];
    acc.x += rv.x; acc.y += rv.y;
    ((float2*)g_h)[(size_t)n * 64 + c] = acc;
}

// ---------------- K7/K8/K9: BN -----------------------------------------------------
__global__ __launch_bounds__(128) void k_bnsum() {
    int b = blockIdx.x, o = threadIdx.x;
    float s = 0.f, sq = 0.f;
    int r0 = b * (NN / NBN), r1 = r0 + (NN / NBN);
    for (int n = r0; n < r1; n++) {
        float v = g_h[(size_t)n * FOUT + o];
        s += v; sq += v * v;
    }
    g_psum[b * FOUT + o] = s;
    g_psq[b * FOUT + o] = sq;
}

__global__ __launch_bounds__(128) void k_bnfin(const float* __restrict__ gamma,
                                               const float* __restrict__ beta) {
    int o = threadIdx.x;
    float s = 0.f, sq = 0.f;
    for (int b = 0; b < NBN; b++) { s += g_psum[b * FOUT + o]; sq += g_psq[b * FOUT + o]; }
    float mean = s / (float)NN;
    float var = sq / (float)NN - mean * mean;
    float sc = gamma[o] * rsqrtf(var + 1e-5f);
    g_scale[o] = sc;
    g_shift[o] = beta[o] - mean * sc;
}

__global__ void k_out(float* __restrict__ out) {
    int i = blockIdx.x * 256 + threadIdx.x;
    if (i < NN * FOUT) {
        int o = i & 127;
        out[i] = g_h[i] * g_scale[o] + g_shift[o];
    }
}

// ---------------- launch -------------------------------------------------------------
extern "C" void kernel_launch(void* const* d_in, const int* in_sizes, int n_in,
                              void* d_out, int out_size) {
    const float* node_feats = (const float*)d_in[0];
    const int*   src        = (const int*)d_in[1];
    const int*   dst        = (const int*)d_in[2];
    const int*   etype      = (const int*)d_in[3];
    const float* norm       = (const float*)d_in[4];
    const float* basis      = (const float*)d_in[5];
    const float* comp       = (const float*)d_in[6];
    const float* h_bias     = (const float*)d_in[7];
    const float* W_res      = (const float*)d_in[8];
    const float* b_res      = (const float*)d_in[9];
    const float* gamma      = (const float*)d_in[10];
    const float* beta       = (const float*)d_in[11];
    float* out = (float*)d_out;

    const int DSMEM   = 3 * ATILE;                      // 104448 B -> 2 CTAs/SM
    const int KW_SMEM = (BB * FIN + RR * BB) * 4;       // 50180 B
    cudaFuncSetAttribute(k_gemm, cudaFuncAttributeMaxDynamicSharedMemorySize, DSMEM);
    cudaFuncSetAttribute(k_w, cudaFuncAttributeMaxDynamicSharedMemorySize, KW_SMEM);

    k_w<<<FIN, 128, KW_SMEM>>>(basis, comp);
    k_xcvt<<<(NN * FIN / 2 + 255) / 256, 256>>>(node_feats);
    k_hist<<<(EE + 255) / 256, 256>>>(etype, dst);
    k_scan1<<<20, 1024>>>();
    k_scan2<<<1, 32>>>();
    k_scan3<<<20, 1024>>>();
    k_scatter<<<(EE + 255) / 256, 256>>>(etype, dst);
    k_gemm<<<GEMM_GRID, 256, DSMEM>>>(src, norm);
    k_res<<<NN / 32, 256>>>(node_feats, W_res, b_res);
    k_reduce<<<NN / 2, 128>>>(h_bias);
    k_bnsum<<<NBN, 128>>>();
    k_bnfin<<<1, 128>>>(gamma, beta);
    k_out<<<(NN * FOUT + 255) / 256, 256>>>(out);
    (void)in_sizes; (void)n_in; (void)out_size;
}

// round 9
// speedup vs baseline: 4.1497x; 1.1444x over previous
#include <cuda_runtime.h>
#include <cuda_fp16.h>
#include <stdint.h>

// Problem constants
#define NN   20000
#define EE   640000
#define FIN  128
#define FOUT 128
#define RR   65
#define BB   65
#define TILE_M 128
#define NBN  100

#define ROWB 272                  // bytes per smem tile row (136 halves, padded)
#define ATILE (128 * ROWB)        // 34816 B
#define GEMM_GRID 296             // 2 CTAs per SM

// ---------------- scratch (__device__ globals) ------------------------------
__device__ __align__(16) __half g_WT[(size_t)RR * FOUT * FIN];   // [r][o][k] fp16
__device__ __align__(16) __half g_xh[(size_t)NN * FIN];
__device__ int   g_cnt[RR];
__device__ int   g_rcur[RR];
__device__ int   g_estart[RR + 1];
__device__ int   g_tstart[RR + 1];
__device__ int   g_perm[EE];
__device__ int   g_dcnt[NN];
__device__ int   g_dcur[NN];
__device__ int   g_dstart[NN + 1];
__device__ int   g_bsum[20];
__device__ int   g_boff[20];
__device__ int   g_dinv[EE];                     // edge -> dst-sorted rank
__device__ __align__(16) __half g_edge_out[(size_t)EE * FOUT]; // dst-rank order
__device__ float g_res[(size_t)NN * FOUT];
__device__ float g_h[(size_t)NN * FOUT];
__device__ float g_psum[NBN * FOUT];
__device__ float g_psq[NBN * FOUT];
__device__ float g_scale[FOUT];
__device__ float g_shift[FOUT];

// ---------------- helpers ----------------------------------------------------
__device__ __forceinline__ uint32_t smem_u32(const void* p) {
    uint32_t a;
    asm("{ .reg .u64 t; cvta.to.shared.u64 t, %1; cvt.u32.u64 %0, t; }"
        : "=r"(a) : "l"(p));
    return a;
}

__device__ __forceinline__ void ldsm_x4(uint32_t addr, uint32_t& r0, uint32_t& r1,
                                        uint32_t& r2, uint32_t& r3) {
    asm volatile("ldmatrix.sync.aligned.m8n8.x4.shared.b16 {%0,%1,%2,%3}, [%4];"
                 : "=r"(r0), "=r"(r1), "=r"(r2), "=r"(r3) : "r"(addr));
}

__device__ __forceinline__ void mma16816(float* c, const uint32_t* a,
                                         uint32_t b0, uint32_t b1) {
    asm volatile(
        "mma.sync.aligned.m16n8k16.row.col.f32.f16.f16.f32 "
        "{%0,%1,%2,%3}, {%4,%5,%6,%7}, {%8,%9}, {%0,%1,%2,%3};"
        : "+f"(c[0]), "+f"(c[1]), "+f"(c[2]), "+f"(c[3])
        : "r"(a[0]), "r"(a[1]), "r"(a[2]), "r"(a[3]), "r"(b0), "r"(b1));
}

__device__ __forceinline__ void cp16(uint32_t dst, const void* src) {
    asm volatile("cp.async.cg.shared.global [%0], [%1], 16;"
                 :: "r"(dst), "l"(src) : "memory");
}
#define CP_COMMIT() asm volatile("cp.async.commit_group;" ::: "memory")
#define CP_WAIT0()  asm volatile("cp.async.wait_group 0;" ::: "memory")

// ---------------- K1: WT fp16 = (comp x basis) transposed, basis read once -----
__global__ __launch_bounds__(128) void k_w(const float* __restrict__ basis,
                                           const float* __restrict__ comp) {
    extern __shared__ float swm[];
    float* sb = swm;              // [BB][FIN] = basis[b][i][o] for fixed i
    float* sc = swm + BB * FIN;   // [RR*BB]

    int i = blockIdx.x, o = threadIdx.x;

    for (int b = 0; b < BB; b++)
        sb[b * FIN + o] = basis[(size_t)b * FIN * FOUT + (size_t)i * FOUT + o];
    for (int idx = o; idx < RR * BB; idx += 128)
        sc[idx] = comp[idx];
    __syncthreads();

    float acc[RR];
    #pragma unroll
    for (int r = 0; r < RR; r++) acc[r] = 0.f;

    for (int b = 0; b < BB; b++) {
        float sv = sb[b * FIN + o];
        #pragma unroll
        for (int r = 0; r < RR; r++)
            acc[r] += sc[r * BB + b] * sv;
    }

    #pragma unroll 1
    for (int r = 0; r < RR; r++)
        g_WT[((size_t)r * FOUT + o) * FIN + i] = __float2half(acc[r]);
}

// ---------------- K1b: x -> fp16; also zero counters ---------------------------
__global__ void k_xcvt(const float* __restrict__ x) {
    int i = blockIdx.x * 256 + threadIdx.x;          // half2 index
    if (i < NN * FIN / 2) {
        float2 v = ((const float2*)x)[i];
        ((__half2*)g_xh)[i] = __floats2half2_rn(v.x, v.y);
    }
    if (i < NN) { g_dcnt[i] = 0; g_dcur[i] = 0; }
    if (i < RR) { g_cnt[i] = 0; g_rcur[i] = 0; }
}

// ---------------- K2: histograms ------------------------------------------------
__global__ void k_hist(const int* __restrict__ etype, const int* __restrict__ dst) {
    __shared__ int sh[RR];
    int tid = threadIdx.x;
    if (tid < RR) sh[tid] = 0;
    __syncthreads();
    int e = blockIdx.x * 256 + tid;
    if (e < EE) {
        atomicAdd(&sh[etype[e]], 1);
        atomicAdd(&g_dcnt[dst[e]], 1);
    }
    __syncthreads();
    if (tid < RR && sh[tid]) atomicAdd(&g_cnt[tid], sh[tid]);
}

// ---------------- K3a: local scans (20 blocks x 1000 counts) --------------------
__global__ __launch_bounds__(1024) void k_scan1() {
    __shared__ int sa[1024], sb2[1024];
    int t = threadIdx.x;
    int g = blockIdx.x * 1000;
    int v = (t < 1000) ? g_dcnt[g + t] : 0;
    sa[t] = v;
    __syncthreads();
    int* in = sa; int* out = sb2;
    #pragma unroll
    for (int off = 1; off < 1024; off <<= 1) {
        out[t] = in[t] + ((t >= off) ? in[t - off] : 0);
        __syncthreads();
        int* tmp = in; in = out; out = tmp;
    }
    if (t < 1000) g_dstart[g + t] = in[t] - v;      // local exclusive
    if (t == 999) g_bsum[blockIdx.x] = in[t];       // block total
}

// ---------------- K3b: block offsets + relation scan ------------------------------
__global__ void k_scan2() {
    if (threadIdx.x == 0) {
        int run = 0;
        for (int k = 0; k < 20; k++) { g_boff[k] = run; run += g_bsum[k]; }
        g_dstart[NN] = run;
        int es = 0, ts = 0;
        for (int r = 0; r < RR; r++) {
            g_estart[r] = es; g_tstart[r] = ts;
            es += g_cnt[r];
            ts += (g_cnt[r] + TILE_M - 1) / TILE_M;
        }
        g_estart[RR] = es; g_tstart[RR] = ts;
    }
}

// ---------------- K3c: add block offsets -------------------------------------------
__global__ __launch_bounds__(1024) void k_scan3() {
    int t = threadIdx.x;
    if (t < 1000) g_dstart[blockIdx.x * 1000 + t] += g_boff[blockIdx.x];
}

// ---------------- K4: scatter ------------------------------------------------------
__global__ void k_scatter(const int* __restrict__ etype, const int* __restrict__ dst) {
    __shared__ int s_cnt[RR], s_base[RR];
    int tid = threadIdx.x;
    if (tid < RR) s_cnt[tid] = 0;
    __syncthreads();
    int e = blockIdx.x * 256 + tid;
    bool valid = (e < EE);
    int r = 0, lrank = 0;
    if (valid) { r = etype[e]; lrank = atomicAdd(&s_cnt[r], 1); }
    __syncthreads();
    if (tid < RR && s_cnt[tid] > 0) s_base[tid] = atomicAdd(&g_rcur[tid], s_cnt[tid]);
    __syncthreads();
    if (valid) {
        g_perm[g_estart[r] + s_base[r] + lrank] = e;
        int d = dst[e];
        g_dinv[e] = g_dstart[d] + atomicAdd(&g_dcur[d], 1);
    }
}

// single-product k-step
#define KSTEP(S, aA) do { \
    uint32_t ka = (aA) + (S) * 32; \
    uint32_t a0[4], a1[4]; \
    ldsm_x4(ka,             a0[0], a0[1], a0[2], a0[3]); \
    ldsm_x4(ka + 16 * ROWB, a1[0], a1[1], a1[2], a1[3]); \
    uint32_t kb = bAddr + (S) * 32; \
    _Pragma("unroll") \
    for (int pr = 0; pr < 4; pr++) { \
        uint32_t b0, b1, b2, b3; \
        ldsm_x4(kb + pr * 16 * ROWB, b0, b1, b2, b3); \
        int nt = pr * 2; \
        mma16816(acc[0][nt],     a0, b0, b1); \
        mma16816(acc[1][nt],     a1, b0, b1); \
        mma16816(acc[0][nt + 1], a0, b2, b3); \
        mma16816(acc[1][nt + 1], a1, b2, b3); \
    } \
} while (0)

// ---------------- K5: persistent HMMA GEMM, single product, 2 CTAs/SM ------------
__global__ __launch_bounds__(256, 2) void k_gemm(const int* __restrict__ src,
                                                 const float* __restrict__ norm) {
    extern __shared__ char dsm[];
    __shared__ int   s_src[2][TILE_M];
    __shared__ float s_nrm[2][TILE_M];
    __shared__ int   s_dinv[2][TILE_M];

    char* Abuf[2] = { dsm, dsm + ATILE };
    char* B = dsm + 2 * ATILE;

    int tid = threadIdx.x;
    int T = g_tstart[RR];
    int per = (T + GEMM_GRID - 1) / GEMM_GRID;
    int t0 = blockIdx.x * per;
    int t1 = t0 + per; if (t1 > T) t1 = T;
    if (t0 >= t1) return;

    int lane = tid & 31, w = tid >> 5;
    int wm = w & 3, wn = w >> 2;
    int rm = wm * 32;
    uint32_t aLane = (uint32_t)((rm + (lane & 15)) * ROWB + ((lane >> 4) << 4));
    uint32_t bLane = (uint32_t)((wn * 64 + ((lane >> 4) << 3) + (lane & 7)) * ROWB
                                + (((lane >> 3) & 1) << 4));
    uint32_t aBase[2] = { smem_u32(Abuf[0]) + aLane, smem_u32(Abuf[1]) + aLane };
    uint32_t bAddr = smem_u32(B) + bLane;

    int r = 0;
    while (g_tstart[r + 1] <= t0) r++;

    // ---- meta for tile t0 (buf 0, sync) ----
    {
        int ebase = g_estart[r] + (t0 - g_tstart[r]) * TILE_M;
        int cnt = g_estart[r + 1] - ebase; if (cnt > TILE_M) cnt = TILE_M;
        if (tid < TILE_M) {
            int sv = 0, dv = -1; float nm = 0.f;
            if (tid < cnt) {
                int e = g_perm[ebase + tid];
                sv = src[e]; nm = norm[e]; dv = g_dinv[e];
            }
            s_src[0][tid] = sv; s_nrm[0][tid] = nm; s_dinv[0][tid] = dv;
        }
    }
    __syncthreads();

    // ---- B fill for first relation + A fill for t0 ----
    {
        const char* WB = (const char*)g_WT + (size_t)r * 32768;
        #pragma unroll
        for (int it = 0; it < 8; it++) {
            int id = tid + it * 256;
            int o = id >> 4, j = id & 15;
            cp16(smem_u32(B + o * ROWB + j * 16), WB + o * 256 + j * 16);
        }
        #pragma unroll
        for (int it = 0; it < 8; it++) {
            int id = tid + it * 256;
            int m = id >> 4, j = id & 15;
            cp16(smem_u32(Abuf[0] + m * ROWB + j * 16),
                 (const char*)g_xh + (size_t)s_src[0][m] * 256 + j * 16);
        }
        CP_COMMIT();
    }
    CP_WAIT0();
    __syncthreads();

    int buf = 0;
    for (int t = t0; t < t1; t++) {
        bool hasNext = (t + 1 < t1);
        int rn = r;
        if (hasNext) { while (g_tstart[rn + 1] <= t + 1) rn++; }

        // 1. meta prefetch for next tile (registers)
        int m_src = 0, m_dinv = -1; float m_nrm = 0.f;
        if (hasNext && tid < TILE_M) {
            int ebase = g_estart[rn] + (t + 1 - g_tstart[rn]) * TILE_M;
            int cnt = g_estart[rn + 1] - ebase; if (cnt > TILE_M) cnt = TILE_M;
            if (tid < cnt) {
                int e = g_perm[ebase + tid];
                m_src = src[e]; m_nrm = norm[e]; m_dinv = g_dinv[e];
            }
        }

        float acc[2][8][4];
        #pragma unroll
        for (int a = 0; a < 2; a++)
            #pragma unroll
            for (int b = 0; b < 8; b++)
                #pragma unroll
                for (int c = 0; c < 4; c++) acc[a][b][c] = 0.f;

        uint32_t aA = aBase[buf];

        // 2. k-steps 0-3 (hide meta LDG)
        #pragma unroll
        for (int s = 0; s < 4; s++) KSTEP(s, aA);

        // 3. publish next meta + A prefetch into other buffer
        if (hasNext && tid < TILE_M) {
            s_src[buf ^ 1][tid] = m_src;
            s_nrm[buf ^ 1][tid] = m_nrm;
            s_dinv[buf ^ 1][tid] = m_dinv;
        }
        __syncthreads();
        if (hasNext) {
            int nb = buf ^ 1;
            #pragma unroll
            for (int it = 0; it < 8; it++) {
                int id = tid + it * 256;
                int m = id >> 4, j = id & 15;
                cp16(smem_u32(Abuf[nb] + m * ROWB + j * 16),
                     (const char*)g_xh + (size_t)s_src[nb][m] * 256 + j * 16);
            }
            CP_COMMIT();
        }

        // 4. k-steps 4-7 (hide A prefetch)
        #pragma unroll
        for (int s = 4; s < 8; s++) KSTEP(s, aA);

        // 5. epilogue: scale by norm, store fp16 rows at dst-rank
        {
            int colBase = wn * 64 + (lane & 3) * 2;
            #pragma unroll
            for (int mt = 0; mt < 2; mt++) {
                int row0 = rm + mt * 16 + (lane >> 2);
                int d0 = s_dinv[buf][row0], d1 = s_dinv[buf][row0 + 8];
                float n0 = s_nrm[buf][row0], n1 = s_nrm[buf][row0 + 8];
                __half* p0 = (d0 >= 0) ? g_edge_out + (size_t)d0 * FOUT + colBase : (__half*)0;
                __half* p1 = (d1 >= 0) ? g_edge_out + (size_t)d1 * FOUT + colBase : (__half*)0;
                #pragma unroll
                for (int nt = 0; nt < 8; nt++) {
                    if (p0) *(__half2*)(p0 + nt * 8) =
                        __floats2half2_rn(acc[mt][nt][0] * n0, acc[mt][nt][1] * n0);
                    if (p1) *(__half2*)(p1 + nt * 8) =
                        __floats2half2_rn(acc[mt][nt][2] * n1, acc[mt][nt][3] * n1);
                }
            }
        }

        // 6. B reload on relation change, then drain A prefetch
        if (hasNext) {
            if (rn != r) {
                __syncthreads();   // all warps done reading B
                const char* WB = (const char*)g_WT + (size_t)rn * 32768;
                #pragma unroll
                for (int it = 0; it < 8; it++) {
                    int id = tid + it * 256;
                    int o = id >> 4, j = id & 15;
                    cp16(smem_u32(B + o * ROWB + j * 16), WB + o * 256 + j * 16);
                }
                CP_COMMIT();
                r = rn;
            }
            CP_WAIT0();
            __syncthreads();
        }
        buf ^= 1;
    }
}

// ---------------- K5b: residual GEMM g_res = relu(x @ W_res + b_res) ------------
__global__ __launch_bounds__(256) void k_res(const float* __restrict__ x,
                                             const float* __restrict__ Wres,
                                             const float* __restrict__ bres) {
    __shared__ float sAT[128][36];
    int tid = threadIdx.x;
    int n0 = blockIdx.x * 32;

    for (int idx = tid; idx < 32 * 32; idx += 256) {
        int i = idx & 31, j = idx >> 5;
        float4 v = __ldg((const float4*)(x + (size_t)(n0 + i) * FIN) + j);
        int k = j << 2;
        sAT[k + 0][i] = v.x; sAT[k + 1][i] = v.y;
        sAT[k + 2][i] = v.z; sAT[k + 3][i] = v.w;
    }
    __syncthreads();

    int tx = tid & 31, ty = tid >> 5;
    const float4* W4 = (const float4*)Wres;
    float c00=0,c01=0,c02=0,c03=0, c10=0,c11=0,c12=0,c13=0;
    float c20=0,c21=0,c22=0,c23=0, c30=0,c31=0,c32=0,c33=0;

    #pragma unroll 4
    for (int k = 0; k < 128; k++) {
        float4 b = __ldg(&W4[(k << 5) + tx]);
        float4 a = *(const float4*)&sAT[k][ty << 2];
        c00 += a.x*b.x; c01 += a.x*b.y; c02 += a.x*b.z; c03 += a.x*b.w;
        c10 += a.y*b.x; c11 += a.y*b.y; c12 += a.y*b.z; c13 += a.y*b.w;
        c20 += a.z*b.x; c21 += a.z*b.y; c22 += a.z*b.z; c23 += a.z*b.w;
        c30 += a.w*b.x; c31 += a.w*b.y; c32 += a.w*b.z; c33 += a.w*b.w;
    }

    float4 br = __ldg(&((const float4*)bres)[tx]);
    float4 rows[4] = {
        make_float4(fmaxf(c00+br.x,0.f), fmaxf(c01+br.y,0.f), fmaxf(c02+br.z,0.f), fmaxf(c03+br.w,0.f)),
        make_float4(fmaxf(c10+br.x,0.f), fmaxf(c11+br.y,0.f), fmaxf(c12+br.z,0.f), fmaxf(c13+br.w,0.f)),
        make_float4(fmaxf(c20+br.x,0.f), fmaxf(c21+br.y,0.f), fmaxf(c22+br.z,0.f), fmaxf(c23+br.w,0.f)),
        make_float4(fmaxf(c30+br.x,0.f), fmaxf(c31+br.y,0.f), fmaxf(c32+br.z,0.f), fmaxf(c33+br.w,0.f))
    };
    #pragma unroll
    for (int i = 0; i < 4; i++)
        *(float4*)(g_res + (size_t)(n0 + (ty << 2) + i) * FOUT + (tx << 2)) = rows[i];
}

// ---------------- K6: segmented reduce (half2 stream) + relu + residual ----------
__global__ __launch_bounds__(128) void k_reduce(const float* __restrict__ h_bias) {
    int n = blockIdx.x * 2 + (threadIdx.x >> 6);
    int c = threadIdx.x & 63;
    int s = g_dstart[n], e = g_dstart[n + 1];
    float2 acc = make_float2(0.f, 0.f);
    const __half2* p = (const __half2*)g_edge_out + (size_t)s * 64 + c;
    for (int j = s; j < e; j++, p += 64) {
        float2 f = __half22float2(*p);
        acc.x += f.x; acc.y += f.y;
    }
    float2 bv = __ldg(&((const float2*)h_bias)[c]);
    acc.x = fmaxf(acc.x + bv.x, 0.f);
    acc.y = fmaxf(acc.y + bv.y, 0.f);
    float2 rv = ((const float2*)g_res)[(size_t)n * 64 + c];
    acc.x += rv.x; acc.y += rv.y;
    ((float2*)g_h)[(size_t)n * 64 + c] = acc;
}

// ---------------- K7/K8/K9: BN -----------------------------------------------------
__global__ __launch_bounds__(128) void k_bnsum() {
    int b = blockIdx.x, o = threadIdx.x;
    float s = 0.f, sq = 0.f;
    int r0 = b * (NN / NBN), r1 = r0 + (NN / NBN);
    for (int n = r0; n < r1; n++) {
        float v = g_h[(size_t)n * FOUT + o];
        s += v; sq += v * v;
    }
    g_psum[b * FOUT + o] = s;
    g_psq[b * FOUT + o] = sq;
}

__global__ __launch_bounds__(128) void k_bnfin(const float* __restrict__ gamma,
                                               const float* __restrict__ beta) {
    int o = threadIdx.x;
    float s = 0.f, sq = 0.f;
    for (int b = 0; b < NBN; b++) { s += g_psum[b * FOUT + o]; sq += g_psq[b * FOUT + o]; }
    float mean = s / (float)NN;
    float var = sq / (float)NN - mean * mean;
    float sc = gamma[o] * rsqrtf(var + 1e-5f);
    g_scale[o] = sc;
    g_shift[o] = beta[o] - mean * sc;
}

__global__ void k_out(float* __restrict__ out) {
    int i = blockIdx.x * 256 + threadIdx.x;
    if (i < NN * FOUT) {
        int o = i & 127;
        out[i] = g_h[i] * g_scale[o] + g_shift[o];
    }
}

// ---------------- launch -------------------------------------------------------------
extern "C" void kernel_launch(void* const* d_in, const int* in_sizes, int n_in,
                              void* d_out, int out_size) {
    const float* node_feats = (const float*)d_in[0];
    const int*   src        = (const int*)d_in[1];
    const int*   dst        = (const int*)d_in[2];
    const int*   etype      = (const int*)d_in[3];
    const float* norm       = (const float*)d_in[4];
    const float* basis      = (const float*)d_in[5];
    const float* comp       = (const float*)d_in[6];
    const float* h_bias     = (const float*)d_in[7];
    const float* W_res      = (const float*)d_in[8];
    const float* b_res      = (const float*)d_in[9];
    const float* gamma      = (const float*)d_in[10];
    const float* beta       = (const float*)d_in[11];
    float* out = (float*)d_out;

    const int DSMEM   = 3 * ATILE;                      // 104448 B -> 2 CTAs/SM
    const int KW_SMEM = (BB * FIN + RR * BB) * 4;       // 50180 B
    cudaFuncSetAttribute(k_gemm, cudaFuncAttributeMaxDynamicSharedMemorySize, DSMEM);
    cudaFuncSetAttribute(k_w, cudaFuncAttributeMaxDynamicSharedMemorySize, KW_SMEM);

    k_w<<<FIN, 128, KW_SMEM>>>(basis, comp);
    k_xcvt<<<(NN * FIN / 2 + 255) / 256, 256>>>(node_feats);
    k_hist<<<(EE + 255) / 256, 256>>>(etype, dst);
    k_scan1<<<20, 1024>>>();
    k_scan2<<<1, 32>>>();
    k_scan3<<<20, 1024>>>();
    k_scatter<<<(EE + 255) / 256, 256>>>(etype, dst);
    k_gemm<<<GEMM_GRID, 256, DSMEM>>>(src, norm);
    k_res<<<NN / 32, 256>>>(node_feats, W_res, b_res);
    k_reduce<<<NN / 2, 128>>>(h_bias);
    k_bnsum<<<NBN, 128>>>();
    k_bnfin<<<1, 128>>>(gamma, beta);
    k_out<<<(NN * FOUT + 255) / 256, 256>>>(out);
    (void)in_sizes; (void)n_in; (void)out_size;
}